// round 14
// baseline (speedup 1.0000x reference)
#include <cuda_runtime.h>
#include <cuda_bf16.h>
#include <stdint.h>
#include <math.h>

#define BB 2
#define NN 2048
#define CC 1024
#define HH 16
#define HD 64
#define MROWS (BB*NN)      // 4096
#define QKVN  (3*CC)       // 3072
#define QKV_ELEMS (BB*HH*NN*HD)   // 4194304

// Scratch (static device arrays — allowed)
__device__ __nv_bfloat16 g_qh[QKV_ELEMS], g_ql[QKV_ELEMS];   // q  [B,H,N,hd]
__device__ __nv_bfloat16 g_kh[QKV_ELEMS], g_kl[QKV_ELEMS];   // k  [B,H,N,hd]
__device__ __nv_bfloat16 g_vh[QKV_ELEMS], g_vl[QKV_ELEMS];   // v  [B,H,N,hd]
__device__ __nv_bfloat16 g_vth[QKV_ELEMS], g_vtl[QKV_ELEMS]; // v^T [B,H,hd,N]
__device__ __nv_bfloat16 g_xh[MROWS*CC],  g_xl[MROWS*CC];    // x hi/lo
__device__ __nv_bfloat16 g_wth[QKVN*CC],  g_wtl[QKVN*CC];    // qkv_w^T hi/lo
__device__ __nv_bfloat16 g_pwth[CC*CC],   g_pwtl[CC*CC];     // proj_w^T hi/lo
__device__ __nv_bfloat16 g_oh[MROWS*CC],  g_ol[MROWS*CC];    // attn out hi/lo

// ---------------------------------------------------------------------------
// helpers
// ---------------------------------------------------------------------------
__device__ __forceinline__ uint32_t smem_to_u32(const void* p) {
    uint32_t a;
    asm("{ .reg .u64 t; cvta.to.shared.u64 t, %1; cvt.u32.u64 %0, t; }"
        : "=r"(a) : "l"(p));
    return a;
}

__device__ __forceinline__ void ldsm4(uint32_t addr, uint32_t* r) {
    asm volatile("ldmatrix.sync.aligned.m8n8.x4.shared.b16 {%0,%1,%2,%3}, [%4];"
                 : "=r"(r[0]), "=r"(r[1]), "=r"(r[2]), "=r"(r[3]) : "r"(addr));
}

__device__ __forceinline__ void mma16816(float* d, const uint32_t* a,
                                         const uint32_t* b) {
    asm volatile(
        "mma.sync.aligned.m16n8k16.row.col.f32.bf16.bf16.f32 "
        "{%0,%1,%2,%3}, {%4,%5,%6,%7}, {%8,%9}, {%0,%1,%2,%3};"
        : "+f"(d[0]), "+f"(d[1]), "+f"(d[2]), "+f"(d[3])
        : "r"(a[0]), "r"(a[1]), "r"(a[2]), "r"(a[3]), "r"(b[0]), "r"(b[1]));
}

__device__ __forceinline__ float ex2(float x) {
    float r; asm("ex2.approx.f32 %0, %1;" : "=f"(r) : "f"(x)); return r;
}

__device__ __forceinline__ void cpa16(uint32_t dst, const void* src) {
    asm volatile("cp.async.cg.shared.global [%0], [%1], 16;" :: "r"(dst), "l"(src));
}
#define CP_COMMIT() asm volatile("cp.async.commit_group;" ::: "memory")
#define CP_WAIT1()  asm volatile("cp.async.wait_group 1;" ::: "memory")
#define CP_WAIT2()  asm volatile("cp.async.wait_group 2;" ::: "memory")

// pack (p0 low, p1 high) as bf16x2; also emit bf16 residual pair
__device__ __forceinline__ void split_pair(float p0, float p1,
                                           uint32_t& hi, uint32_t& lo) {
    __nv_bfloat16 h0 = __float2bfloat16_rn(p0);
    __nv_bfloat16 h1 = __float2bfloat16_rn(p1);
    hi = ((uint32_t)__bfloat16_as_ushort(h1) << 16) | __bfloat16_as_ushort(h0);
    float r0 = p0 - __bfloat162float(h0);
    float r1 = p1 - __bfloat162float(h1);
    asm("cvt.rn.bf16x2.f32 %0, %1, %2;" : "=r"(lo) : "f"(r1), "f"(r0));
}

// ---------------------------------------------------------------------------
// x -> bf16 hi/lo (same layout)
// ---------------------------------------------------------------------------
__global__ __launch_bounds__(256)
void convert_x_kernel(const float* __restrict__ x)
{
    const int i = (blockIdx.x * 256 + threadIdx.x) * 4;
    float4 f = *(const float4*)(x + i);
    uint32_t h01, l01, h23, l23;
    split_pair(f.x, f.y, h01, l01);
    split_pair(f.z, f.w, h23, l23);
    *(uint2*)(g_xh + i) = make_uint2(h01, h23);
    *(uint2*)(g_xl + i) = make_uint2(l01, l23);
}

// ---------------------------------------------------------------------------
// Weight transpose+convert: src fp32 [R][C] -> dsth/dstl bf16 [C][R]
// ---------------------------------------------------------------------------
__global__ __launch_bounds__(256)
void transpose_convert_kernel(const float* __restrict__ src,
                              __nv_bfloat16* __restrict__ dsth,
                              __nv_bfloat16* __restrict__ dstl,
                              int R, int C)
{
    __shared__ float t[32][33];
    const int bx = blockIdx.x * 32;   // over C
    const int by = blockIdx.y * 32;   // over R
    const int x = threadIdx.x, y0 = threadIdx.y;
    #pragma unroll
    for (int i = y0; i < 32; i += 8)
        t[i][x] = src[(size_t)(by + i) * C + bx + x];
    __syncthreads();
    #pragma unroll
    for (int i = y0; i < 32; i += 8) {
        float v = t[x][i];
        __nv_bfloat16 h = __float2bfloat16_rn(v);
        dsth[(size_t)(bx + i) * R + by + x] = h;
        dstl[(size_t)(bx + i) * R + by + x] = __float2bfloat16_rn(v - __bfloat162float(h));
    }
}

// ---------------------------------------------------------------------------
// v transpose (bf16): per (b,h): [NN][HD] -> [HD][NN], both hi and lo
// ---------------------------------------------------------------------------
__global__ __launch_bounds__(256)
void transpose_v_kernel()
{
    __shared__ ushort th[32][33];
    __shared__ ushort tl[32][33];
    const int bh = blockIdx.z;
    const int by = blockIdx.x * 32;    // over N
    const int bx = blockIdx.y * 32;    // over hd
    const int x = threadIdx.x, y0 = threadIdx.y;
    const size_t sbase = (size_t)bh * NN * HD;
    #pragma unroll
    for (int i = y0; i < 32; i += 8) {
        th[i][x] = __bfloat16_as_ushort(g_vh[sbase + (size_t)(by + i) * HD + bx + x]);
        tl[i][x] = __bfloat16_as_ushort(g_vl[sbase + (size_t)(by + i) * HD + bx + x]);
    }
    __syncthreads();
    #pragma unroll
    for (int i = y0; i < 32; i += 8) {
        g_vth[sbase + (size_t)(bx + i) * NN + by + x] = __ushort_as_bfloat16(th[x][i]);
        g_vtl[sbase + (size_t)(bx + i) * NN + by + x] = __ushort_as_bfloat16(tl[x][i]);
    }
}

// ---------------------------------------------------------------------------
// cp.async 3-stage HMMA GEMM, 3-PASS mma ordering (break RAW chains):
// pass A: a_hi*b_hi, pass B: a_hi*b_lo, pass C: a_lo*b_hi.
// Per-accumulator term order unchanged (hh->hl->lh) => bit-identical results.
// mode 0: QKV epilogue -> bias + fused rmsnorm q/k -> bf16 hi/lo scatter
// mode 1: proj epilogue -> bias -> fp32 row-major out
// ---------------------------------------------------------------------------
__device__ __forceinline__ uint32_t swz(int row, int kbyte) {   // 64B rows
    return (uint32_t)(row * 64 + ((kbyte & 48) ^ (((row >> 1) & 3) << 4)) + (kbyte & 15));
}

#define GEMM_SMEM 98304

__global__ __launch_bounds__(256, 2)
void hmma_gemm_ca(const __nv_bfloat16* __restrict__ Ah, const __nv_bfloat16* __restrict__ Al,
                  const __nv_bfloat16* __restrict__ Bh, const __nv_bfloat16* __restrict__ Bl,
                  const float* __restrict__ bias, float* __restrict__ out,
                  const float* __restrict__ qnw, const float* __restrict__ knw,
                  int mode)
{
    extern __shared__ __align__(128) char sb[];
    const uint32_t sbu = smem_to_u32(sb);

    const int tid  = threadIdx.x;
    const int lane = tid & 31;
    const int w    = tid >> 5;
    const int wm   = (w >> 1) * 32;
    const int wn   = (w & 1) * 64;
    const int row0 = blockIdx.y * 128;
    const int col0 = blockIdx.x * 128;

    const int amat = lane >> 3;
    const int arow_off = (amat & 1) * 8 + (lane & 7);
    const int akb_off  = (amat >> 1) * 16;
    const int brow_off = (amat >> 1) * 8 + (lane & 7);
    const int bkb_off  = (amat & 1) * 16;

    const int ch_row0 = (tid + 0)   >> 2, ch_kc0 = (tid + 0)   & 3;
    const int ch_row1 = (tid + 256) >> 2, ch_kc1 = (tid + 256) & 3;

    auto load_stage = [&](int kt, int slot) {
        const uint32_t base = sbu + (uint32_t)slot * 32768u;
        {
            const uint32_t off = swz(ch_row0, ch_kc0 * 16);
            const size_t as = (size_t)(row0 + ch_row0) * CC + kt * 32 + ch_kc0 * 8;
            const size_t bs = (size_t)(col0 + ch_row0) * CC + kt * 32 + ch_kc0 * 8;
            cpa16(base + off,         Ah + as);
            cpa16(base + 8192 + off,  Al + as);
            cpa16(base + 16384 + off, Bh + bs);
            cpa16(base + 24576 + off, Bl + bs);
        }
        {
            const uint32_t off = swz(ch_row1, ch_kc1 * 16);
            const size_t as = (size_t)(row0 + ch_row1) * CC + kt * 32 + ch_kc1 * 8;
            const size_t bs = (size_t)(col0 + ch_row1) * CC + kt * 32 + ch_kc1 * 8;
            cpa16(base + off,         Ah + as);
            cpa16(base + 8192 + off,  Al + as);
            cpa16(base + 16384 + off, Bh + bs);
            cpa16(base + 24576 + off, Bl + bs);
        }
    };

    float D[2][8][4];
    #pragma unroll
    for (int i = 0; i < 2; i++)
        #pragma unroll
        for (int j = 0; j < 8; j++)
            #pragma unroll
            for (int c = 0; c < 4; c++) D[i][j][c] = 0.f;

    load_stage(0, 0); CP_COMMIT();
    load_stage(1, 1); CP_COMMIT();
    load_stage(2, 2); CP_COMMIT();

    int slot = 0;
    for (int t = 0; t < 32; t++) {
        CP_WAIT2();
        __syncthreads();
        const uint32_t stb = sbu + (uint32_t)slot * 32768u;

        #pragma unroll
        for (int k16 = 0; k16 < 2; k16++) {
            const int kb = k16 * 32;
            uint32_t a_hi[2][4], a_lo[2][4];
            #pragma unroll
            for (int i = 0; i < 2; i++) {
                const uint32_t aoff = swz(wm + 16*i + arow_off, kb + akb_off);
                ldsm4(stb + aoff, a_hi[i]);
                ldsm4(stb + 8192 + aoff, a_lo[i]);
            }
            // pass A: a_hi * b_hi
            #pragma unroll
            for (int j2 = 0; j2 < 4; j2++) {
                const uint32_t boff = swz(wn + j2*16 + brow_off, kb + bkb_off);
                uint32_t b[4];
                ldsm4(stb + 16384 + boff, b);
                #pragma unroll
                for (int i = 0; i < 2; i++) {
                    mma16816(D[i][2*j2],   a_hi[i], b);
                    mma16816(D[i][2*j2+1], a_hi[i], b + 2);
                }
            }
            // pass B: a_hi * b_lo
            #pragma unroll
            for (int j2 = 0; j2 < 4; j2++) {
                const uint32_t boff = swz(wn + j2*16 + brow_off, kb + bkb_off);
                uint32_t b[4];
                ldsm4(stb + 24576 + boff, b);
                #pragma unroll
                for (int i = 0; i < 2; i++) {
                    mma16816(D[i][2*j2],   a_hi[i], b);
                    mma16816(D[i][2*j2+1], a_hi[i], b + 2);
                }
            }
            // pass C: a_lo * b_hi
            #pragma unroll
            for (int j2 = 0; j2 < 4; j2++) {
                const uint32_t boff = swz(wn + j2*16 + brow_off, kb + bkb_off);
                uint32_t b[4];
                ldsm4(stb + 16384 + boff, b);
                #pragma unroll
                for (int i = 0; i < 2; i++) {
                    mma16816(D[i][2*j2],   a_lo[i], b);
                    mma16816(D[i][2*j2+1], a_lo[i], b + 2);
                }
            }
        }
        __syncthreads();
        if (t + 3 < 32) load_stage(t + 3, slot);
        CP_COMMIT();                      // always commit (uniform accounting)
        slot = (slot == 2) ? 0 : slot + 1;
    }

    // ---- Epilogue ----
    const int g = lane >> 2;
    const int t4 = lane & 3;
    const int colw = col0 + wn;
    const int s   = (mode == 0) ? (colw >> 10) : 3;
    const int h   = (colw & 1023) >> 6;
    const float* nw = (s == 0) ? qnw : knw;
    const float postscale = (s == 0) ? 0.18033688011112042f : 1.0f; // 0.125*log2(e)
    __nv_bfloat16* dsth = (s == 0) ? g_qh : (s == 1) ? g_kh : g_vh;
    __nv_bfloat16* dstl = (s == 0) ? g_ql : (s == 1) ? g_kl : g_vl;

    #pragma unroll
    for (int i = 0; i < 2; i++) {
        float v0[16], v1[16];
        #pragma unroll
        for (int j = 0; j < 8; j++) {
            const float bj0 = bias[colw + 8*j + 2*t4];
            const float bj1 = bias[colw + 8*j + 2*t4 + 1];
            v0[2*j]   = D[i][j][0] + bj0;
            v0[2*j+1] = D[i][j][1] + bj1;
            v1[2*j]   = D[i][j][2] + bj0;
            v1[2*j+1] = D[i][j][3] + bj1;
        }
        if (mode == 0 && s < 2) {
            float ss0 = 0.f, ss1 = 0.f;
            #pragma unroll
            for (int c = 0; c < 16; c++) { ss0 += v0[c]*v0[c]; ss1 += v1[c]*v1[c]; }
            ss0 += __shfl_xor_sync(0xffffffffu, ss0, 1);
            ss0 += __shfl_xor_sync(0xffffffffu, ss0, 2);
            ss1 += __shfl_xor_sync(0xffffffffu, ss1, 1);
            ss1 += __shfl_xor_sync(0xffffffffu, ss1, 2);
            const float n0 = rsqrtf(ss0 * (1.0f/64.0f) + 1e-6f) * postscale;
            const float n1 = rsqrtf(ss1 * (1.0f/64.0f) + 1e-6f) * postscale;
            #pragma unroll
            for (int j = 0; j < 8; j++) {
                const float w0 = nw[8*j + 2*t4], w1 = nw[8*j + 2*t4 + 1];
                v0[2*j]   *= n0 * w0;  v0[2*j+1] *= n0 * w1;
                v1[2*j]   *= n1 * w0;  v1[2*j+1] *= n1 * w1;
            }
        }
        const int gr0 = row0 + wm + 16*i + g;
        const int gr1 = gr0 + 8;
        if (mode == 0) {
            const int b0r = gr0 >> 11, n0r = gr0 & 2047;
            const int b1r = gr1 >> 11, n1r = gr1 & 2047;
            const size_t p0 = (((size_t)(b0r * HH + h) * NN) + n0r) * HD;
            const size_t p1 = (((size_t)(b1r * HH + h) * NN) + n1r) * HD;
            #pragma unroll
            for (int j = 0; j < 8; j++) {
                uint32_t hi, lo;
                split_pair(v0[2*j], v0[2*j+1], hi, lo);
                *(uint32_t*)(dsth + p0 + 8*j + 2*t4) = hi;
                *(uint32_t*)(dstl + p0 + 8*j + 2*t4) = lo;
                split_pair(v1[2*j], v1[2*j+1], hi, lo);
                *(uint32_t*)(dsth + p1 + 8*j + 2*t4) = hi;
                *(uint32_t*)(dstl + p1 + 8*j + 2*t4) = lo;
            }
        } else {
            float* p0 = out + (size_t)gr0 * CC + colw;
            float* p1 = out + (size_t)gr1 * CC + colw;
            #pragma unroll
            for (int j = 0; j < 8; j++) {
                *(float2*)(p0 + 8*j + 2*t4) = make_float2(v0[2*j], v0[2*j+1]);
                *(float2*)(p1 + 8*j + 2*t4) = make_float2(v1[2*j], v1[2*j+1]);
            }
        }
    }
}

// ---------------------------------------------------------------------------
// HMMA flash attention (128 threads, 64-q tile, 2 blocks/SM), fixed-max
// softmax, 3-PASS mma ordering in both S and PV (break RAW chains).
// SMEM 80KB: Q hi/lo [64][64] @0/8K; stage s @16K+s*32K:
//   Khi/Klo [64][64] @+0/+8K, Vthi/Vtlo [64 d][64 k] @+16K/+24K.
// ---------------------------------------------------------------------------
__device__ __forceinline__ uint32_t swz_qk(int row, int kbyte) {   // 128B rows
    return (uint32_t)(row * 128 + ((((kbyte >> 4) ^ row) & 7) << 4) + (kbyte & 15));
}

#define ATTN_SMEM 81920
#define MAXB 13.0f

__global__ __launch_bounds__(128, 2)
void attn_kernel()
{
    extern __shared__ __align__(128) char smem[];
    const uint32_t sbu = smem_to_u32(smem);

    const int tid  = threadIdx.x;
    const int lane = tid & 31;
    const int w    = tid >> 5;     // 0..3
    const int wm   = w * 16;
    const int g = lane >> 2, t = lane & 3;

    const int bh = blockIdx.y;
    const int b  = bh >> 4, h = bh & 15;
    const int qt = blockIdx.x;     // 0..31

    const size_t qoff  = ((size_t)bh * NN + qt * 64) * HD;
    const size_t kbase = (size_t)bh * NN * HD;
    const size_t vtbase = (size_t)bh * HD * NN;

    const int amat = lane >> 3;
    const int arow_off = (amat & 1) * 8 + (lane & 7);
    const int akb_off  = (amat >> 1) * 16;
    const int brow_off = (amat >> 1) * 8 + (lane & 7);
    const int bkb_off  = (amat & 1) * 16;

    // ---- stage loader: K + Vt, 64-key tile, 4 chunks/thread/buffer ----
    auto load_stage = [&](int kt, int slot) {
        const uint32_t base = sbu + 16384u + (uint32_t)slot * 32768u;
        #pragma unroll
        for (int c = 0; c < 4; c++) {
            const int idx = tid + 128 * c;
            const int row = idx >> 3;
            const int kc  = idx & 7;
            const uint32_t off = swz_qk(row, kc * 16);
            const size_t ks = kbase + (size_t)(kt * 64 + row) * HD + kc * 8;
            const size_t vs = vtbase + (size_t)row * NN + kt * 64 + kc * 8;
            cpa16(base + off,          g_kh + ks);
            cpa16(base + 8192 + off,   g_kl + ks);
            cpa16(base + 16384 + off,  g_vth + vs);
            cpa16(base + 24576 + off,  g_vtl + vs);
        }
    };

    load_stage(0, 0); CP_COMMIT();
    load_stage(1, 1); CP_COMMIT();

    // ---- load Q tile (plain 16B copies) ----
    #pragma unroll
    for (int c = 0; c < 4; c++) {
        const int idx = tid + 128 * c;
        const int row = idx >> 3;
        const int kc  = idx & 7;
        const uint32_t off = swz_qk(row, kc * 16);
        *(uint4*)(smem + off)        = *(const uint4*)(g_qh + qoff + (size_t)row * HD + kc * 8);
        *(uint4*)(smem + 8192 + off) = *(const uint4*)(g_ql + qoff + (size_t)row * HD + kc * 8);
    }
    __syncthreads();

    // ---- Q fragments (16 rows x 64 hd) ----
    uint32_t qh[4][4], ql[4][4];
    #pragma unroll
    for (int kk = 0; kk < 4; kk++) {
        const uint32_t off = swz_qk(wm + arow_off, kk*32 + akb_off);
        ldsm4(sbu + off, qh[kk]);
        ldsm4(sbu + 8192 + off, ql[kk]);
    }

    float l0 = 0.f, l1 = 0.f;
    float O[8][4];
    #pragma unroll
    for (int j = 0; j < 8; j++)
        #pragma unroll
        for (int c = 0; c < 4; c++) O[j][c] = 0.f;

    for (int kt = 0; kt < NN / 64; kt++) {
        CP_WAIT1();
        __syncthreads();
        const uint32_t stb = sbu + 16384u + (uint32_t)(kt & 1) * 32768u;

        // ---- S = Q K^T (64 keys), 3-pass per kk ----
        float S[8][4];
        #pragma unroll
        for (int j = 0; j < 8; j++)
            #pragma unroll
            for (int c = 0; c < 4; c++) S[j][c] = 0.f;

        #pragma unroll
        for (int kk = 0; kk < 4; kk++) {
            // pass A: qh * khh
            #pragma unroll
            for (int j2 = 0; j2 < 4; j2++) {
                const uint32_t off = swz_qk(j2*16 + brow_off, kk*32 + bkb_off);
                uint32_t bb[4];
                ldsm4(stb + off, bb);
                mma16816(S[2*j2],   qh[kk], bb);
                mma16816(S[2*j2+1], qh[kk], bb + 2);
            }
            // pass B: qh * kll
            #pragma unroll
            for (int j2 = 0; j2 < 4; j2++) {
                const uint32_t off = swz_qk(j2*16 + brow_off, kk*32 + bkb_off);
                uint32_t bb[4];
                ldsm4(stb + 8192 + off, bb);
                mma16816(S[2*j2],   qh[kk], bb);
                mma16816(S[2*j2+1], qh[kk], bb + 2);
            }
            // pass C: ql * khh
            #pragma unroll
            for (int j2 = 0; j2 < 4; j2++) {
                const uint32_t off = swz_qk(j2*16 + brow_off, kk*32 + bkb_off);
                uint32_t bb[4];
                ldsm4(stb + off, bb);
                mma16816(S[2*j2],   ql[kk], bb);
                mma16816(S[2*j2+1], ql[kk], bb + 2);
            }
        }

        // ---- fixed-max softmax: p = ex2(s - MAXB); accumulate local sums ----
        #pragma unroll
        for (int j = 0; j < 8; j++) {
            S[j][0] = ex2(S[j][0] - MAXB);
            S[j][1] = ex2(S[j][1] - MAXB);
            S[j][2] = ex2(S[j][2] - MAXB);
            S[j][3] = ex2(S[j][3] - MAXB);
            l0 += S[j][0] + S[j][1];
            l1 += S[j][2] + S[j][3];
        }

        // ---- O += P V, 3-pass per kk ----
        #pragma unroll
        for (int kk = 0; kk < 4; kk++) {
            uint32_t phi[4], plo[4];
            split_pair(S[2*kk][0],   S[2*kk][1],   phi[0], plo[0]);
            split_pair(S[2*kk][2],   S[2*kk][3],   phi[1], plo[1]);
            split_pair(S[2*kk+1][0], S[2*kk+1][1], phi[2], plo[2]);
            split_pair(S[2*kk+1][2], S[2*kk+1][3], phi[3], plo[3]);
            // pass A: phi * vh
            #pragma unroll
            for (int jh = 0; jh < 4; jh++) {
                const uint32_t off = swz_qk(jh*16 + brow_off, kk*32 + bkb_off);
                uint32_t vv[4];
                ldsm4(stb + 16384 + off, vv);
                mma16816(O[2*jh],   phi, vv);
                mma16816(O[2*jh+1], phi, vv + 2);
            }
            // pass B: phi * vl
            #pragma unroll
            for (int jh = 0; jh < 4; jh++) {
                const uint32_t off = swz_qk(jh*16 + brow_off, kk*32 + bkb_off);
                uint32_t vv[4];
                ldsm4(stb + 24576 + off, vv);
                mma16816(O[2*jh],   phi, vv);
                mma16816(O[2*jh+1], phi, vv + 2);
            }
            // pass C: plo * vh
            #pragma unroll
            for (int jh = 0; jh < 4; jh++) {
                const uint32_t off = swz_qk(jh*16 + brow_off, kk*32 + bkb_off);
                uint32_t vv[4];
                ldsm4(stb + 16384 + off, vv);
                mma16816(O[2*jh],   plo, vv);
                mma16816(O[2*jh+1], plo, vv + 2);
            }
        }
        __syncthreads();
        if (kt + 2 < NN / 64) load_stage(kt + 2, kt & 1);
        CP_COMMIT();                      // always commit (uniform accounting)
    }

    // ---- deferred row-sum reduction (once) ----
    l0 += __shfl_xor_sync(0xffffffffu, l0, 1);
    l0 += __shfl_xor_sync(0xffffffffu, l0, 2);
    l1 += __shfl_xor_sync(0xffffffffu, l1, 1);
    l1 += __shfl_xor_sync(0xffffffffu, l1, 2);

    // ---- epilogue: normalize, write bf16 hi/lo to g_oh/g_ol [B,N,C] ----
    const float inv0 = 1.0f / l0;
    const float inv1 = 1.0f / l1;
    const int q0 = qt * 64 + wm + g;
    const size_t p0 = ((size_t)b * NN + q0) * CC + h * HD;
    const size_t p1 = ((size_t)b * NN + q0 + 8) * CC + h * HD;
    #pragma unroll
    for (int j = 0; j < 8; j++) {
        uint32_t hi, lo;
        split_pair(O[j][0] * inv0, O[j][1] * inv0, hi, lo);
        *(uint32_t*)(g_oh + p0 + 8*j + 2*t) = hi;
        *(uint32_t*)(g_ol + p0 + 8*j + 2*t) = lo;
        split_pair(O[j][2] * inv1, O[j][3] * inv1, hi, lo);
        *(uint32_t*)(g_oh + p1 + 8*j + 2*t) = hi;
        *(uint32_t*)(g_ol + p1 + 8*j + 2*t) = lo;
    }
}

// ---------------------------------------------------------------------------
extern "C" void kernel_launch(void* const* d_in, const int* in_sizes, int n_in,
                              void* d_out, int out_size)
{
    const float* x        = (const float*)d_in[0];
    const float* qkv_w    = (const float*)d_in[1];
    const float* qkv_b    = (const float*)d_in[2];
    const float* q_norm_w = (const float*)d_in[3];
    const float* k_norm_w = (const float*)d_in[4];
    const float* proj_w   = (const float*)d_in[5];
    const float* proj_b   = (const float*)d_in[6];
    float* out = (float*)d_out;

    __nv_bfloat16 *xh, *xl, *wth, *wtl, *pwth, *pwtl, *oh, *ol;
    cudaGetSymbolAddress((void**)&xh,   g_xh);
    cudaGetSymbolAddress((void**)&xl,   g_xl);
    cudaGetSymbolAddress((void**)&wth,  g_wth);
    cudaGetSymbolAddress((void**)&wtl,  g_wtl);
    cudaGetSymbolAddress((void**)&pwth, g_pwth);
    cudaGetSymbolAddress((void**)&pwtl, g_pwtl);
    cudaGetSymbolAddress((void**)&oh,   g_oh);
    cudaGetSymbolAddress((void**)&ol,   g_ol);

    cudaFuncSetAttribute(hmma_gemm_ca,
                         cudaFuncAttributeMaxDynamicSharedMemorySize, GEMM_SMEM);
    cudaFuncSetAttribute(attn_kernel,
                         cudaFuncAttributeMaxDynamicSharedMemorySize, ATTN_SMEM);

    // Operand conversion
    convert_x_kernel<<<MROWS * CC / 1024, 256>>>(x);
    {
        dim3 tb(32, 8);
        transpose_convert_kernel<<<dim3(QKVN/32, CC/32), tb>>>(qkv_w, wth, wtl, CC, QKVN);
        transpose_convert_kernel<<<dim3(CC/32, CC/32), tb>>>(proj_w, pwth, pwtl, CC, CC);
    }
    // QKV GEMM + bias + fused rmsnorm -> bf16 hi/lo q/k/v
    {
        dim3 grid(QKVN / 128, MROWS / 128);   // 24 x 32
        hmma_gemm_ca<<<grid, 256, GEMM_SMEM>>>(xh, xl, wth, wtl, qkv_b, nullptr,
                                               q_norm_w, k_norm_w, 0);
    }
    // v transpose (bf16 -> [B,H,hd,N])
    {
        dim3 tb(32, 8);
        transpose_v_kernel<<<dim3(NN/32, HD/32, BB*HH), tb>>>();
    }
    // Flash attention (128 threads, 64-q tile, fixed-max softmax, 3-pass mma)
    {
        dim3 grid(NN / 64, BB * HH);          // 32 x 32
        attn_kernel<<<grid, 128, ATTN_SMEM>>>();
    }
    // Output projection
    {
        dim3 grid(CC / 128, MROWS / 128);     // 8 x 32
        hmma_gemm_ca<<<grid, 256, GEMM_SMEM>>>(oh, ol, pwth, pwtl, proj_b, out,
                                               nullptr, nullptr, 1);
    }
}

// round 15
// speedup vs baseline: 1.0553x; 1.0553x over previous
#include <cuda_runtime.h>
#include <cuda_bf16.h>
#include <stdint.h>
#include <math.h>

#define BB 2
#define NN 2048
#define CC 1024
#define HH 16
#define HD 64
#define MROWS (BB*NN)      // 4096
#define QKVN  (3*CC)       // 3072
#define QKV_ELEMS (BB*HH*NN*HD)   // 4194304

// Scratch (static device arrays — allowed)
__device__ __nv_bfloat16 g_qh[QKV_ELEMS], g_ql[QKV_ELEMS];   // q  [B,H,N,hd]
__device__ __nv_bfloat16 g_kh[QKV_ELEMS], g_kl[QKV_ELEMS];   // k  [B,H,N,hd]
__device__ __nv_bfloat16 g_vth[QKV_ELEMS], g_vtl[QKV_ELEMS]; // v^T [B,H,hd,N]
__device__ __nv_bfloat16 g_xh[MROWS*CC],  g_xl[MROWS*CC];    // x hi/lo
__device__ __nv_bfloat16 g_wth[QKVN*CC],  g_wtl[QKVN*CC];    // qkv_w^T hi/lo
__device__ __nv_bfloat16 g_pwth[CC*CC],   g_pwtl[CC*CC];     // proj_w^T hi/lo
__device__ __nv_bfloat16 g_oh[MROWS*CC],  g_ol[MROWS*CC];    // attn out hi/lo

// ---------------------------------------------------------------------------
// helpers
// ---------------------------------------------------------------------------
__device__ __forceinline__ uint32_t smem_to_u32(const void* p) {
    uint32_t a;
    asm("{ .reg .u64 t; cvta.to.shared.u64 t, %1; cvt.u32.u64 %0, t; }"
        : "=r"(a) : "l"(p));
    return a;
}

__device__ __forceinline__ void ldsm4(uint32_t addr, uint32_t* r) {
    asm volatile("ldmatrix.sync.aligned.m8n8.x4.shared.b16 {%0,%1,%2,%3}, [%4];"
                 : "=r"(r[0]), "=r"(r[1]), "=r"(r[2]), "=r"(r[3]) : "r"(addr));
}

__device__ __forceinline__ void mma16816(float* d, const uint32_t* a,
                                         const uint32_t* b) {
    asm volatile(
        "mma.sync.aligned.m16n8k16.row.col.f32.bf16.bf16.f32 "
        "{%0,%1,%2,%3}, {%4,%5,%6,%7}, {%8,%9}, {%0,%1,%2,%3};"
        : "+f"(d[0]), "+f"(d[1]), "+f"(d[2]), "+f"(d[3])
        : "r"(a[0]), "r"(a[1]), "r"(a[2]), "r"(a[3]), "r"(b[0]), "r"(b[1]));
}

__device__ __forceinline__ float ex2(float x) {
    float r; asm("ex2.approx.f32 %0, %1;" : "=f"(r) : "f"(x)); return r;
}

__device__ __forceinline__ void cpa16(uint32_t dst, const void* src) {
    asm volatile("cp.async.cg.shared.global [%0], [%1], 16;" :: "r"(dst), "l"(src));
}
#define CP_COMMIT() asm volatile("cp.async.commit_group;" ::: "memory")
#define CP_WAIT1()  asm volatile("cp.async.wait_group 1;" ::: "memory")

// pack (p0 low, p1 high) as bf16x2; also emit bf16 residual pair
__device__ __forceinline__ void split_pair(float p0, float p1,
                                           uint32_t& hi, uint32_t& lo) {
    __nv_bfloat16 h0 = __float2bfloat16_rn(p0);
    __nv_bfloat16 h1 = __float2bfloat16_rn(p1);
    hi = ((uint32_t)__bfloat16_as_ushort(h1) << 16) | __bfloat16_as_ushort(h0);
    float r0 = p0 - __bfloat162float(h0);
    float r1 = p1 - __bfloat162float(h1);
    asm("cvt.rn.bf16x2.f32 %0, %1, %2;" : "=r"(lo) : "f"(r1), "f"(r0));
}

// ---------------------------------------------------------------------------
// x -> bf16 hi/lo (same layout)
// ---------------------------------------------------------------------------
__global__ __launch_bounds__(256)
void convert_x_kernel(const float* __restrict__ x)
{
    const int i = (blockIdx.x * 256 + threadIdx.x) * 4;
    float4 f = *(const float4*)(x + i);
    uint32_t h01, l01, h23, l23;
    split_pair(f.x, f.y, h01, l01);
    split_pair(f.z, f.w, h23, l23);
    *(uint2*)(g_xh + i) = make_uint2(h01, h23);
    *(uint2*)(g_xl + i) = make_uint2(l01, l23);
}

// ---------------------------------------------------------------------------
// Weight transpose+convert: src fp32 [R][C] -> dsth/dstl bf16 [C][R]
// ---------------------------------------------------------------------------
__global__ __launch_bounds__(256)
void transpose_convert_kernel(const float* __restrict__ src,
                              __nv_bfloat16* __restrict__ dsth,
                              __nv_bfloat16* __restrict__ dstl,
                              int R, int C)
{
    __shared__ float t[32][33];
    const int bx = blockIdx.x * 32;   // over C
    const int by = blockIdx.y * 32;   // over R
    const int x = threadIdx.x, y0 = threadIdx.y;
    #pragma unroll
    for (int i = y0; i < 32; i += 8)
        t[i][x] = src[(size_t)(by + i) * C + bx + x];
    __syncthreads();
    #pragma unroll
    for (int i = y0; i < 32; i += 8) {
        float v = t[x][i];
        __nv_bfloat16 h = __float2bfloat16_rn(v);
        dsth[(size_t)(bx + i) * R + by + x] = h;
        dstl[(size_t)(bx + i) * R + by + x] = __float2bfloat16_rn(v - __bfloat162float(h));
    }
}

// ---------------------------------------------------------------------------
// cp.async 3-stage HMMA GEMM, SINGLE barrier per k-iteration:
// prefetch for iter t+2 into slot (t+2)%3 == (t-1)%3 at the bottom of iter t
// (safe: top barrier of iter t proves all warps finished iter t-1, the last
// reader of that slot). cp.async.wait_group 1 at top completes stage t.
// mode 0: QKV epilogue -> bias + fused rmsnorm q/k -> bf16 hi/lo scatter;
//         v third is written TRANSPOSED into g_vth/g_vtl ([B,H,hd,N]).
// mode 1: proj epilogue -> bias -> fp32 row-major out
// ---------------------------------------------------------------------------
__device__ __forceinline__ uint32_t swz(int row, int kbyte) {   // 64B rows
    return (uint32_t)(row * 64 + ((kbyte & 48) ^ (((row >> 1) & 3) << 4)) + (kbyte & 15));
}

#define GEMM_SMEM 98304

__global__ __launch_bounds__(256, 2)
void hmma_gemm_ca(const __nv_bfloat16* __restrict__ Ah, const __nv_bfloat16* __restrict__ Al,
                  const __nv_bfloat16* __restrict__ Bh, const __nv_bfloat16* __restrict__ Bl,
                  const float* __restrict__ bias, float* __restrict__ out,
                  const float* __restrict__ qnw, const float* __restrict__ knw,
                  int mode)
{
    extern __shared__ __align__(128) char sb[];
    const uint32_t sbu = smem_to_u32(sb);

    const int tid  = threadIdx.x;
    const int lane = tid & 31;
    const int w    = tid >> 5;
    const int wm   = (w >> 1) * 32;
    const int wn   = (w & 1) * 64;
    const int row0 = blockIdx.y * 128;
    const int col0 = blockIdx.x * 128;

    const int amat = lane >> 3;
    const int arow_off = (amat & 1) * 8 + (lane & 7);
    const int akb_off  = (amat >> 1) * 16;
    const int brow_off = (amat >> 1) * 8 + (lane & 7);
    const int bkb_off  = (amat & 1) * 16;

    const int ch_row0 = (tid + 0)   >> 2, ch_kc0 = (tid + 0)   & 3;
    const int ch_row1 = (tid + 256) >> 2, ch_kc1 = (tid + 256) & 3;

    auto load_stage = [&](int kt, int slot) {
        const uint32_t base = sbu + (uint32_t)slot * 32768u;
        {
            const uint32_t off = swz(ch_row0, ch_kc0 * 16);
            const size_t as = (size_t)(row0 + ch_row0) * CC + kt * 32 + ch_kc0 * 8;
            const size_t bs = (size_t)(col0 + ch_row0) * CC + kt * 32 + ch_kc0 * 8;
            cpa16(base + off,         Ah + as);
            cpa16(base + 8192 + off,  Al + as);
            cpa16(base + 16384 + off, Bh + bs);
            cpa16(base + 24576 + off, Bl + bs);
        }
        {
            const uint32_t off = swz(ch_row1, ch_kc1 * 16);
            const size_t as = (size_t)(row0 + ch_row1) * CC + kt * 32 + ch_kc1 * 8;
            const size_t bs = (size_t)(col0 + ch_row1) * CC + kt * 32 + ch_kc1 * 8;
            cpa16(base + off,         Ah + as);
            cpa16(base + 8192 + off,  Al + as);
            cpa16(base + 16384 + off, Bh + bs);
            cpa16(base + 24576 + off, Bl + bs);
        }
    };

    float D[2][8][4];
    #pragma unroll
    for (int i = 0; i < 2; i++)
        #pragma unroll
        for (int j = 0; j < 8; j++)
            #pragma unroll
            for (int c = 0; c < 4; c++) D[i][j][c] = 0.f;

    load_stage(0, 0); CP_COMMIT();
    load_stage(1, 1); CP_COMMIT();

    for (int t = 0; t < 32; t++) {
        CP_WAIT1();                       // stage t landed (pending <= {t+1})
        __syncthreads();                  // all warps: data visible, iter t-1 done
        const uint32_t stb = sbu + (uint32_t)(t % 3) * 32768u;

        #pragma unroll
        for (int k16 = 0; k16 < 2; k16++) {
            const int kb = k16 * 32;
            uint32_t a_hi[2][4], a_lo[2][4];
            #pragma unroll
            for (int i = 0; i < 2; i++) {
                const uint32_t aoff = swz(wm + 16*i + arow_off, kb + akb_off);
                ldsm4(stb + aoff, a_hi[i]);
                ldsm4(stb + 8192 + aoff, a_lo[i]);
            }
            #pragma unroll
            for (int j2 = 0; j2 < 4; j2++) {
                const uint32_t boff = swz(wn + j2*16 + brow_off, kb + bkb_off);
                uint32_t b_hi[4], b_lo[4];
                ldsm4(stb + 16384 + boff, b_hi);
                ldsm4(stb + 24576 + boff, b_lo);
                #pragma unroll
                for (int i = 0; i < 2; i++) {
                    mma16816(D[i][2*j2],   a_hi[i], b_hi);
                    mma16816(D[i][2*j2],   a_hi[i], b_lo);
                    mma16816(D[i][2*j2],   a_lo[i], b_hi);
                    mma16816(D[i][2*j2+1], a_hi[i], b_hi + 2);
                    mma16816(D[i][2*j2+1], a_hi[i], b_lo + 2);
                    mma16816(D[i][2*j2+1], a_lo[i], b_hi + 2);
                }
            }
        }
        // prefetch iter t+2 into slot (t+2)%3 == (t-1)%3 — no barrier needed
        if (t + 2 < 32) load_stage(t + 2, (t + 2) % 3);
        CP_COMMIT();                      // always commit (uniform accounting)
    }

    // ---- Epilogue ----
    const int g = lane >> 2;
    const int t4 = lane & 3;
    const int colw = col0 + wn;
    const int s   = (mode == 0) ? (colw >> 10) : 3;
    const int h   = (colw & 1023) >> 6;
    const float* nw = (s == 0) ? qnw : knw;
    const float postscale = (s == 0) ? 0.18033688011112042f : 1.0f; // 0.125*log2(e)

    #pragma unroll
    for (int i = 0; i < 2; i++) {
        float v0[16], v1[16];
        #pragma unroll
        for (int j = 0; j < 8; j++) {
            const float bj0 = bias[colw + 8*j + 2*t4];
            const float bj1 = bias[colw + 8*j + 2*t4 + 1];
            v0[2*j]   = D[i][j][0] + bj0;
            v0[2*j+1] = D[i][j][1] + bj1;
            v1[2*j]   = D[i][j][2] + bj0;
            v1[2*j+1] = D[i][j][3] + bj1;
        }
        const int gr0 = row0 + wm + 16*i + g;
        const int gr1 = gr0 + 8;
        if (mode == 0) {
            const int b0r = gr0 >> 11, n0r = gr0 & 2047;
            const int b1r = gr1 >> 11, n1r = gr1 & 2047;
            if (s < 2) {
                float ss0 = 0.f, ss1 = 0.f;
                #pragma unroll
                for (int c = 0; c < 16; c++) { ss0 += v0[c]*v0[c]; ss1 += v1[c]*v1[c]; }
                ss0 += __shfl_xor_sync(0xffffffffu, ss0, 1);
                ss0 += __shfl_xor_sync(0xffffffffu, ss0, 2);
                ss1 += __shfl_xor_sync(0xffffffffu, ss1, 1);
                ss1 += __shfl_xor_sync(0xffffffffu, ss1, 2);
                const float n0 = rsqrtf(ss0 * (1.0f/64.0f) + 1e-6f) * postscale;
                const float n1 = rsqrtf(ss1 * (1.0f/64.0f) + 1e-6f) * postscale;
                #pragma unroll
                for (int j = 0; j < 8; j++) {
                    const float w0 = nw[8*j + 2*t4], w1 = nw[8*j + 2*t4 + 1];
                    v0[2*j]   *= n0 * w0;  v0[2*j+1] *= n0 * w1;
                    v1[2*j]   *= n1 * w0;  v1[2*j+1] *= n1 * w1;
                }
                __nv_bfloat16* dsth = (s == 0) ? g_qh : g_kh;
                __nv_bfloat16* dstl = (s == 0) ? g_ql : g_kl;
                const size_t p0 = (((size_t)(b0r * HH + h) * NN) + n0r) * HD;
                const size_t p1 = (((size_t)(b1r * HH + h) * NN) + n1r) * HD;
                #pragma unroll
                for (int j = 0; j < 8; j++) {
                    uint32_t hi, lo;
                    split_pair(v0[2*j], v0[2*j+1], hi, lo);
                    *(uint32_t*)(dsth + p0 + 8*j + 2*t4) = hi;
                    *(uint32_t*)(dstl + p0 + 8*j + 2*t4) = lo;
                    split_pair(v1[2*j], v1[2*j+1], hi, lo);
                    *(uint32_t*)(dsth + p1 + 8*j + 2*t4) = hi;
                    *(uint32_t*)(dstl + p1 + 8*j + 2*t4) = lo;
                }
            } else {
                // v third: write TRANSPOSED into g_vth/g_vtl [B,H,hd,N]
                const size_t vb0 = (size_t)(b0r * HH + h) * HD * NN;
                const size_t vb1 = (size_t)(b1r * HH + h) * HD * NN;
                #pragma unroll
                for (int j = 0; j < 8; j++) {
                    #pragma unroll
                    for (int c = 0; c < 2; c++) {
                        const int d = 8*j + 2*t4 + c;
                        float f0 = v0[2*j + c];
                        float f1 = v1[2*j + c];
                        __nv_bfloat16 h0 = __float2bfloat16_rn(f0);
                        __nv_bfloat16 h1 = __float2bfloat16_rn(f1);
                        g_vth[vb0 + (size_t)d * NN + n0r] = h0;
                        g_vtl[vb0 + (size_t)d * NN + n0r] =
                            __float2bfloat16_rn(f0 - __bfloat162float(h0));
                        g_vth[vb1 + (size_t)d * NN + n1r] = h1;
                        g_vtl[vb1 + (size_t)d * NN + n1r] =
                            __float2bfloat16_rn(f1 - __bfloat162float(h1));
                    }
                }
            }
        } else {
            float* p0 = out + (size_t)gr0 * CC + colw;
            float* p1 = out + (size_t)gr1 * CC + colw;
            #pragma unroll
            for (int j = 0; j < 8; j++) {
                *(float2*)(p0 + 8*j + 2*t4) = make_float2(v0[2*j], v0[2*j+1]);
                *(float2*)(p1 + 8*j + 2*t4) = make_float2(v1[2*j], v1[2*j+1]);
            }
        }
    }
}

// ---------------------------------------------------------------------------
// HMMA flash attention (128 threads, 64-q tile, 2 blocks/SM), fixed-max
// softmax, 3-stage cp.async ring with a SINGLE barrier per key-tile
// (same safety argument as the GEMM).
// SMEM 112KB: Q hi/lo [64][64] @0/8K; stage s @16K+s*32K:
//   Khi/Klo [64][64] @+0/+8K, Vthi/Vtlo [64 d][64 k] @+16K/+24K.
// ---------------------------------------------------------------------------
__device__ __forceinline__ uint32_t swz_qk(int row, int kbyte) {   // 128B rows
    return (uint32_t)(row * 128 + ((((kbyte >> 4) ^ row) & 7) << 4) + (kbyte & 15));
}

#define ATTN_SMEM (16384 + 3*32768)   // 114688
#define MAXB 13.0f

__global__ __launch_bounds__(128, 2)
void attn_kernel()
{
    extern __shared__ __align__(128) char smem[];
    const uint32_t sbu = smem_to_u32(smem);

    const int tid  = threadIdx.x;
    const int lane = tid & 31;
    const int w    = tid >> 5;     // 0..3
    const int wm   = w * 16;
    const int g = lane >> 2, t = lane & 3;

    const int bh = blockIdx.y;
    const int b  = bh >> 4, h = bh & 15;
    const int qt = blockIdx.x;     // 0..31

    const size_t qoff  = ((size_t)bh * NN + qt * 64) * HD;
    const size_t kbase = (size_t)bh * NN * HD;
    const size_t vtbase = (size_t)bh * HD * NN;

    const int amat = lane >> 3;
    const int arow_off = (amat & 1) * 8 + (lane & 7);
    const int akb_off  = (amat >> 1) * 16;
    const int brow_off = (amat >> 1) * 8 + (lane & 7);
    const int bkb_off  = (amat & 1) * 16;

    // ---- stage loader: K + Vt, 64-key tile, 4 chunks/thread/buffer ----
    auto load_stage = [&](int kt, int slot) {
        const uint32_t base = sbu + 16384u + (uint32_t)slot * 32768u;
        #pragma unroll
        for (int c = 0; c < 4; c++) {
            const int idx = tid + 128 * c;
            const int row = idx >> 3;
            const int kc  = idx & 7;
            const uint32_t off = swz_qk(row, kc * 16);
            const size_t ks = kbase + (size_t)(kt * 64 + row) * HD + kc * 8;
            const size_t vs = vtbase + (size_t)row * NN + kt * 64 + kc * 8;
            cpa16(base + off,          g_kh + ks);
            cpa16(base + 8192 + off,   g_kl + ks);
            cpa16(base + 16384 + off,  g_vth + vs);
            cpa16(base + 24576 + off,  g_vtl + vs);
        }
    };

    load_stage(0, 0); CP_COMMIT();
    load_stage(1, 1); CP_COMMIT();

    // ---- load Q tile (plain 16B copies) ----
    #pragma unroll
    for (int c = 0; c < 4; c++) {
        const int idx = tid + 128 * c;
        const int row = idx >> 3;
        const int kc  = idx & 7;
        const uint32_t off = swz_qk(row, kc * 16);
        *(uint4*)(smem + off)        = *(const uint4*)(g_qh + qoff + (size_t)row * HD + kc * 8);
        *(uint4*)(smem + 8192 + off) = *(const uint4*)(g_ql + qoff + (size_t)row * HD + kc * 8);
    }
    __syncthreads();

    // ---- Q fragments (16 rows x 64 hd) ----
    uint32_t qh[4][4], ql[4][4];
    #pragma unroll
    for (int kk = 0; kk < 4; kk++) {
        const uint32_t off = swz_qk(wm + arow_off, kk*32 + akb_off);
        ldsm4(sbu + off, qh[kk]);
        ldsm4(sbu + 8192 + off, ql[kk]);
    }

    float l0 = 0.f, l1 = 0.f;
    float O[8][4];
    #pragma unroll
    for (int j = 0; j < 8; j++)
        #pragma unroll
        for (int c = 0; c < 4; c++) O[j][c] = 0.f;

    for (int kt = 0; kt < NN / 64; kt++) {
        CP_WAIT1();                       // stage kt landed
        __syncthreads();                  // all warps past iter kt-1
        const uint32_t stb = sbu + 16384u + (uint32_t)(kt % 3) * 32768u;

        // ---- S = Q K^T (64 keys) ----
        float S[8][4];
        #pragma unroll
        for (int j = 0; j < 8; j++)
            #pragma unroll
            for (int c = 0; c < 4; c++) S[j][c] = 0.f;

        #pragma unroll
        for (int kk = 0; kk < 4; kk++) {
            #pragma unroll
            for (int j2 = 0; j2 < 4; j2++) {
                const uint32_t off = swz_qk(j2*16 + brow_off, kk*32 + bkb_off);
                uint32_t bhh[4], bll[4];
                ldsm4(stb + off, bhh);
                ldsm4(stb + 8192 + off, bll);
                mma16816(S[2*j2],   qh[kk], bhh);
                mma16816(S[2*j2],   qh[kk], bll);
                mma16816(S[2*j2],   ql[kk], bhh);
                mma16816(S[2*j2+1], qh[kk], bhh + 2);
                mma16816(S[2*j2+1], qh[kk], bll + 2);
                mma16816(S[2*j2+1], ql[kk], bhh + 2);
            }
        }

        // ---- fixed-max softmax: p = ex2(s - MAXB); accumulate local sums ----
        #pragma unroll
        for (int j = 0; j < 8; j++) {
            S[j][0] = ex2(S[j][0] - MAXB);
            S[j][1] = ex2(S[j][1] - MAXB);
            S[j][2] = ex2(S[j][2] - MAXB);
            S[j][3] = ex2(S[j][3] - MAXB);
            l0 += S[j][0] + S[j][1];
            l1 += S[j][2] + S[j][3];
        }

        // ---- O += P V (P from S fragments; Vt B-operand) ----
        #pragma unroll
        for (int kk = 0; kk < 4; kk++) {
            uint32_t phi[4], plo[4];
            split_pair(S[2*kk][0],   S[2*kk][1],   phi[0], plo[0]);
            split_pair(S[2*kk][2],   S[2*kk][3],   phi[1], plo[1]);
            split_pair(S[2*kk+1][0], S[2*kk+1][1], phi[2], plo[2]);
            split_pair(S[2*kk+1][2], S[2*kk+1][3], phi[3], plo[3]);
            #pragma unroll
            for (int jh = 0; jh < 4; jh++) {
                const uint32_t off = swz_qk(jh*16 + brow_off, kk*32 + bkb_off);
                uint32_t vh[4], vl[4];
                ldsm4(stb + 16384 + off, vh);
                ldsm4(stb + 24576 + off, vl);
                mma16816(O[2*jh],   phi, vh);
                mma16816(O[2*jh],   phi, vl);
                mma16816(O[2*jh],   plo, vh);
                mma16816(O[2*jh+1], phi, vh + 2);
                mma16816(O[2*jh+1], phi, vl + 2);
                mma16816(O[2*jh+1], plo, vh + 2);
            }
        }
        // prefetch kt+2 into slot (kt+2)%3 == (kt-1)%3 — no barrier needed
        if (kt + 2 < NN / 64) load_stage(kt + 2, (kt + 2) % 3);
        CP_COMMIT();                      // always commit (uniform accounting)
    }

    // ---- deferred row-sum reduction (once) ----
    l0 += __shfl_xor_sync(0xffffffffu, l0, 1);
    l0 += __shfl_xor_sync(0xffffffffu, l0, 2);
    l1 += __shfl_xor_sync(0xffffffffu, l1, 1);
    l1 += __shfl_xor_sync(0xffffffffu, l1, 2);

    // ---- epilogue: normalize, write bf16 hi/lo to g_oh/g_ol [B,N,C] ----
    const float inv0 = 1.0f / l0;
    const float inv1 = 1.0f / l1;
    const int q0 = qt * 64 + wm + g;
    const size_t p0 = ((size_t)b * NN + q0) * CC + h * HD;
    const size_t p1 = ((size_t)b * NN + q0 + 8) * CC + h * HD;
    #pragma unroll
    for (int j = 0; j < 8; j++) {
        uint32_t hi, lo;
        split_pair(O[j][0] * inv0, O[j][1] * inv0, hi, lo);
        *(uint32_t*)(g_oh + p0 + 8*j + 2*t) = hi;
        *(uint32_t*)(g_ol + p0 + 8*j + 2*t) = lo;
        split_pair(O[j][2] * inv1, O[j][3] * inv1, hi, lo);
        *(uint32_t*)(g_oh + p1 + 8*j + 2*t) = hi;
        *(uint32_t*)(g_ol + p1 + 8*j + 2*t) = lo;
    }
}

// ---------------------------------------------------------------------------
extern "C" void kernel_launch(void* const* d_in, const int* in_sizes, int n_in,
                              void* d_out, int out_size)
{
    const float* x        = (const float*)d_in[0];
    const float* qkv_w    = (const float*)d_in[1];
    const float* qkv_b    = (const float*)d_in[2];
    const float* q_norm_w = (const float*)d_in[3];
    const float* k_norm_w = (const float*)d_in[4];
    const float* proj_w   = (const float*)d_in[5];
    const float* proj_b   = (const float*)d_in[6];
    float* out = (float*)d_out;

    __nv_bfloat16 *xh, *xl, *wth, *wtl, *pwth, *pwtl, *oh, *ol;
    cudaGetSymbolAddress((void**)&xh,   g_xh);
    cudaGetSymbolAddress((void**)&xl,   g_xl);
    cudaGetSymbolAddress((void**)&wth,  g_wth);
    cudaGetSymbolAddress((void**)&wtl,  g_wtl);
    cudaGetSymbolAddress((void**)&pwth, g_pwth);
    cudaGetSymbolAddress((void**)&pwtl, g_pwtl);
    cudaGetSymbolAddress((void**)&oh,   g_oh);
    cudaGetSymbolAddress((void**)&ol,   g_ol);

    cudaFuncSetAttribute(hmma_gemm_ca,
                         cudaFuncAttributeMaxDynamicSharedMemorySize, GEMM_SMEM);
    cudaFuncSetAttribute(attn_kernel,
                         cudaFuncAttributeMaxDynamicSharedMemorySize, ATTN_SMEM);

    // Operand conversion
    convert_x_kernel<<<MROWS * CC / 1024, 256>>>(x);
    {
        dim3 tb(32, 8);
        transpose_convert_kernel<<<dim3(QKVN/32, CC/32), tb>>>(qkv_w, wth, wtl, CC, QKVN);
        transpose_convert_kernel<<<dim3(CC/32, CC/32), tb>>>(proj_w, pwth, pwtl, CC, CC);
    }
    // QKV GEMM + bias + fused rmsnorm -> bf16 hi/lo q/k, v written transposed
    {
        dim3 grid(QKVN / 128, MROWS / 128);   // 24 x 32
        hmma_gemm_ca<<<grid, 256, GEMM_SMEM>>>(xh, xl, wth, wtl, qkv_b, nullptr,
                                               q_norm_w, k_norm_w, 0);
    }
    // Flash attention (128 threads, 64-q tile, fixed-max softmax, 1-sync pipe)
    {
        dim3 grid(NN / 64, BB * HH);          // 32 x 32
        attn_kernel<<<grid, 128, ATTN_SMEM>>>();
    }
    // Output projection
    {
        dim3 grid(CC / 128, MROWS / 128);     // 8 x 32
        hmma_gemm_ca<<<grid, 256, GEMM_SMEM>>>(oh, ol, pwth, pwtl, proj_b, out,
                                               nullptr, nullptr, 1);
    }
}

// round 16
// speedup vs baseline: 1.4589x; 1.3825x over previous
#include <cuda_runtime.h>
#include <cuda_bf16.h>
#include <cuda_fp16.h>
#include <stdint.h>
#include <math.h>

#define BB 2
#define NN 2048
#define CC 1024
#define HH 16
#define HD 64
#define MROWS (BB*NN)      // 4096
#define QKVN  (3*CC)       // 3072
#define QKV_ELEMS (BB*HH*NN*HD)   // 4194304

// Scratch (static device arrays — allowed)
__device__ __half g_qf[QKV_ELEMS];                           // q fp16 [B,H,N,hd]
__device__ __half g_kf[QKV_ELEMS];                           // k fp16 [B,H,N,hd]
__device__ __half g_vtf[QKV_ELEMS];                          // v^T fp16 [B,H,hd,N]
__device__ __nv_bfloat16 g_xh[MROWS*CC],  g_xl[MROWS*CC];    // x hi/lo
__device__ __nv_bfloat16 g_wth[QKVN*CC],  g_wtl[QKVN*CC];    // qkv_w^T hi/lo
__device__ __nv_bfloat16 g_pwth[CC*CC],   g_pwtl[CC*CC];     // proj_w^T hi/lo
__device__ __nv_bfloat16 g_oh[MROWS*CC],  g_ol[MROWS*CC];    // attn out hi/lo

// ---------------------------------------------------------------------------
// helpers
// ---------------------------------------------------------------------------
__device__ __forceinline__ uint32_t smem_to_u32(const void* p) {
    uint32_t a;
    asm("{ .reg .u64 t; cvta.to.shared.u64 t, %1; cvt.u32.u64 %0, t; }"
        : "=r"(a) : "l"(p));
    return a;
}

__device__ __forceinline__ void ldsm4(uint32_t addr, uint32_t* r) {
    asm volatile("ldmatrix.sync.aligned.m8n8.x4.shared.b16 {%0,%1,%2,%3}, [%4];"
                 : "=r"(r[0]), "=r"(r[1]), "=r"(r[2]), "=r"(r[3]) : "r"(addr));
}

__device__ __forceinline__ void mma16816(float* d, const uint32_t* a,
                                         const uint32_t* b) {
    asm volatile(
        "mma.sync.aligned.m16n8k16.row.col.f32.bf16.bf16.f32 "
        "{%0,%1,%2,%3}, {%4,%5,%6,%7}, {%8,%9}, {%0,%1,%2,%3};"
        : "+f"(d[0]), "+f"(d[1]), "+f"(d[2]), "+f"(d[3])
        : "r"(a[0]), "r"(a[1]), "r"(a[2]), "r"(a[3]), "r"(b[0]), "r"(b[1]));
}

__device__ __forceinline__ void mma16816h(float* d, const uint32_t* a,
                                          const uint32_t* b) {
    asm volatile(
        "mma.sync.aligned.m16n8k16.row.col.f32.f16.f16.f32 "
        "{%0,%1,%2,%3}, {%4,%5,%6,%7}, {%8,%9}, {%0,%1,%2,%3};"
        : "+f"(d[0]), "+f"(d[1]), "+f"(d[2]), "+f"(d[3])
        : "r"(a[0]), "r"(a[1]), "r"(a[2]), "r"(a[3]), "r"(b[0]), "r"(b[1]));
}

__device__ __forceinline__ float ex2(float x) {
    float r; asm("ex2.approx.f32 %0, %1;" : "=f"(r) : "f"(x)); return r;
}

__device__ __forceinline__ void cpa16(uint32_t dst, const void* src) {
    asm volatile("cp.async.cg.shared.global [%0], [%1], 16;" :: "r"(dst), "l"(src));
}
#define CP_COMMIT() asm volatile("cp.async.commit_group;" ::: "memory")
#define CP_WAIT1()  asm volatile("cp.async.wait_group 1;" ::: "memory")

// pack (p0 low, p1 high) as bf16x2; also emit bf16 residual pair
__device__ __forceinline__ void split_pair(float p0, float p1,
                                           uint32_t& hi, uint32_t& lo) {
    __nv_bfloat16 h0 = __float2bfloat16_rn(p0);
    __nv_bfloat16 h1 = __float2bfloat16_rn(p1);
    hi = ((uint32_t)__bfloat16_as_ushort(h1) << 16) | __bfloat16_as_ushort(h0);
    float r0 = p0 - __bfloat162float(h0);
    float r1 = p1 - __bfloat162float(h1);
    asm("cvt.rn.bf16x2.f32 %0, %1, %2;" : "=r"(lo) : "f"(r1), "f"(r0));
}

// pack (lo, hi) floats into one f16x2 register
__device__ __forceinline__ uint32_t packh2(float lo, float hi) {
    uint32_t r;
    asm("cvt.rn.f16x2.f32 %0, %1, %2;" : "=r"(r) : "f"(hi), "f"(lo));
    return r;
}

// ---------------------------------------------------------------------------
// x -> bf16 hi/lo (same layout)
// ---------------------------------------------------------------------------
__global__ __launch_bounds__(256)
void convert_x_kernel(const float* __restrict__ x)
{
    const int i = (blockIdx.x * 256 + threadIdx.x) * 4;
    float4 f = *(const float4*)(x + i);
    uint32_t h01, l01, h23, l23;
    split_pair(f.x, f.y, h01, l01);
    split_pair(f.z, f.w, h23, l23);
    *(uint2*)(g_xh + i) = make_uint2(h01, h23);
    *(uint2*)(g_xl + i) = make_uint2(l01, l23);
}

// ---------------------------------------------------------------------------
// Weight transpose+convert: src fp32 [R][C] -> dsth/dstl bf16 [C][R]
// ---------------------------------------------------------------------------
__global__ __launch_bounds__(256)
void transpose_convert_kernel(const float* __restrict__ src,
                              __nv_bfloat16* __restrict__ dsth,
                              __nv_bfloat16* __restrict__ dstl,
                              int R, int C)
{
    __shared__ float t[32][33];
    const int bx = blockIdx.x * 32;   // over C
    const int by = blockIdx.y * 32;   // over R
    const int x = threadIdx.x, y0 = threadIdx.y;
    #pragma unroll
    for (int i = y0; i < 32; i += 8)
        t[i][x] = src[(size_t)(by + i) * C + bx + x];
    __syncthreads();
    #pragma unroll
    for (int i = y0; i < 32; i += 8) {
        float v = t[x][i];
        __nv_bfloat16 h = __float2bfloat16_rn(v);
        dsth[(size_t)(bx + i) * R + by + x] = h;
        dstl[(size_t)(bx + i) * R + by + x] = __float2bfloat16_rn(v - __bfloat162float(h));
    }
}

// ---------------------------------------------------------------------------
// cp.async 3-stage HMMA GEMM, single barrier per k-iteration (round-15 WIN).
// mode 0: QKV epilogue -> bias + fused rmsnorm q/k -> fp16 scatter;
//         v third written TRANSPOSED fp16 into g_vtf ([B,H,hd,N]).
// mode 1: proj epilogue -> bias -> fp32 row-major out
// ---------------------------------------------------------------------------
__device__ __forceinline__ uint32_t swz(int row, int kbyte) {   // 64B rows
    return (uint32_t)(row * 64 + ((kbyte & 48) ^ (((row >> 1) & 3) << 4)) + (kbyte & 15));
}

#define GEMM_SMEM 98304

__global__ __launch_bounds__(256, 2)
void hmma_gemm_ca(const __nv_bfloat16* __restrict__ Ah, const __nv_bfloat16* __restrict__ Al,
                  const __nv_bfloat16* __restrict__ Bh, const __nv_bfloat16* __restrict__ Bl,
                  const float* __restrict__ bias, float* __restrict__ out,
                  const float* __restrict__ qnw, const float* __restrict__ knw,
                  int mode)
{
    extern __shared__ __align__(128) char sb[];
    const uint32_t sbu = smem_to_u32(sb);

    const int tid  = threadIdx.x;
    const int lane = tid & 31;
    const int w    = tid >> 5;
    const int wm   = (w >> 1) * 32;
    const int wn   = (w & 1) * 64;
    const int row0 = blockIdx.y * 128;
    const int col0 = blockIdx.x * 128;

    const int amat = lane >> 3;
    const int arow_off = (amat & 1) * 8 + (lane & 7);
    const int akb_off  = (amat >> 1) * 16;
    const int brow_off = (amat >> 1) * 8 + (lane & 7);
    const int bkb_off  = (amat & 1) * 16;

    const int ch_row0 = (tid + 0)   >> 2, ch_kc0 = (tid + 0)   & 3;
    const int ch_row1 = (tid + 256) >> 2, ch_kc1 = (tid + 256) & 3;

    auto load_stage = [&](int kt, int slot) {
        const uint32_t base = sbu + (uint32_t)slot * 32768u;
        {
            const uint32_t off = swz(ch_row0, ch_kc0 * 16);
            const size_t as = (size_t)(row0 + ch_row0) * CC + kt * 32 + ch_kc0 * 8;
            const size_t bs = (size_t)(col0 + ch_row0) * CC + kt * 32 + ch_kc0 * 8;
            cpa16(base + off,         Ah + as);
            cpa16(base + 8192 + off,  Al + as);
            cpa16(base + 16384 + off, Bh + bs);
            cpa16(base + 24576 + off, Bl + bs);
        }
        {
            const uint32_t off = swz(ch_row1, ch_kc1 * 16);
            const size_t as = (size_t)(row0 + ch_row1) * CC + kt * 32 + ch_kc1 * 8;
            const size_t bs = (size_t)(col0 + ch_row1) * CC + kt * 32 + ch_kc1 * 8;
            cpa16(base + off,         Ah + as);
            cpa16(base + 8192 + off,  Al + as);
            cpa16(base + 16384 + off, Bh + bs);
            cpa16(base + 24576 + off, Bl + bs);
        }
    };

    float D[2][8][4];
    #pragma unroll
    for (int i = 0; i < 2; i++)
        #pragma unroll
        for (int j = 0; j < 8; j++)
            #pragma unroll
            for (int c = 0; c < 4; c++) D[i][j][c] = 0.f;

    load_stage(0, 0); CP_COMMIT();
    load_stage(1, 1); CP_COMMIT();

    for (int t = 0; t < 32; t++) {
        CP_WAIT1();
        __syncthreads();
        const uint32_t stb = sbu + (uint32_t)(t % 3) * 32768u;

        #pragma unroll
        for (int k16 = 0; k16 < 2; k16++) {
            const int kb = k16 * 32;
            uint32_t a_hi[2][4], a_lo[2][4];
            #pragma unroll
            for (int i = 0; i < 2; i++) {
                const uint32_t aoff = swz(wm + 16*i + arow_off, kb + akb_off);
                ldsm4(stb + aoff, a_hi[i]);
                ldsm4(stb + 8192 + aoff, a_lo[i]);
            }
            #pragma unroll
            for (int j2 = 0; j2 < 4; j2++) {
                const uint32_t boff = swz(wn + j2*16 + brow_off, kb + bkb_off);
                uint32_t b_hi[4], b_lo[4];
                ldsm4(stb + 16384 + boff, b_hi);
                ldsm4(stb + 24576 + boff, b_lo);
                #pragma unroll
                for (int i = 0; i < 2; i++) {
                    mma16816(D[i][2*j2],   a_hi[i], b_hi);
                    mma16816(D[i][2*j2],   a_hi[i], b_lo);
                    mma16816(D[i][2*j2],   a_lo[i], b_hi);
                    mma16816(D[i][2*j2+1], a_hi[i], b_hi + 2);
                    mma16816(D[i][2*j2+1], a_hi[i], b_lo + 2);
                    mma16816(D[i][2*j2+1], a_lo[i], b_hi + 2);
                }
            }
        }
        if (t + 2 < 32) load_stage(t + 2, (t + 2) % 3);
        CP_COMMIT();                      // always commit (uniform accounting)
    }

    // ---- Epilogue ----
    const int g = lane >> 2;
    const int t4 = lane & 3;
    const int colw = col0 + wn;
    const int s   = (mode == 0) ? (colw >> 10) : 3;
    const int h   = (colw & 1023) >> 6;
    const float* nw = (s == 0) ? qnw : knw;
    const float postscale = (s == 0) ? 0.18033688011112042f : 1.0f; // 0.125*log2(e)

    #pragma unroll
    for (int i = 0; i < 2; i++) {
        float v0[16], v1[16];
        #pragma unroll
        for (int j = 0; j < 8; j++) {
            const float bj0 = bias[colw + 8*j + 2*t4];
            const float bj1 = bias[colw + 8*j + 2*t4 + 1];
            v0[2*j]   = D[i][j][0] + bj0;
            v0[2*j+1] = D[i][j][1] + bj1;
            v1[2*j]   = D[i][j][2] + bj0;
            v1[2*j+1] = D[i][j][3] + bj1;
        }
        const int gr0 = row0 + wm + 16*i + g;
        const int gr1 = gr0 + 8;
        if (mode == 0) {
            const int b0r = gr0 >> 11, n0r = gr0 & 2047;
            const int b1r = gr1 >> 11, n1r = gr1 & 2047;
            if (s < 2) {
                float ss0 = 0.f, ss1 = 0.f;
                #pragma unroll
                for (int c = 0; c < 16; c++) { ss0 += v0[c]*v0[c]; ss1 += v1[c]*v1[c]; }
                ss0 += __shfl_xor_sync(0xffffffffu, ss0, 1);
                ss0 += __shfl_xor_sync(0xffffffffu, ss0, 2);
                ss1 += __shfl_xor_sync(0xffffffffu, ss1, 1);
                ss1 += __shfl_xor_sync(0xffffffffu, ss1, 2);
                const float n0 = rsqrtf(ss0 * (1.0f/64.0f) + 1e-6f) * postscale;
                const float n1 = rsqrtf(ss1 * (1.0f/64.0f) + 1e-6f) * postscale;
                #pragma unroll
                for (int j = 0; j < 8; j++) {
                    const float w0 = nw[8*j + 2*t4], w1 = nw[8*j + 2*t4 + 1];
                    v0[2*j]   *= n0 * w0;  v0[2*j+1] *= n0 * w1;
                    v1[2*j]   *= n1 * w0;  v1[2*j+1] *= n1 * w1;
                }
                __half* dst = (s == 0) ? g_qf : g_kf;
                const size_t p0 = (((size_t)(b0r * HH + h) * NN) + n0r) * HD;
                const size_t p1 = (((size_t)(b1r * HH + h) * NN) + n1r) * HD;
                #pragma unroll
                for (int j = 0; j < 8; j++) {
                    *(uint32_t*)(dst + p0 + 8*j + 2*t4) = packh2(v0[2*j], v0[2*j+1]);
                    *(uint32_t*)(dst + p1 + 8*j + 2*t4) = packh2(v1[2*j], v1[2*j+1]);
                }
            } else {
                // v third: write TRANSPOSED fp16 into g_vtf [B,H,hd,N]
                const size_t vb0 = (size_t)(b0r * HH + h) * HD * NN;
                const size_t vb1 = (size_t)(b1r * HH + h) * HD * NN;
                #pragma unroll
                for (int j = 0; j < 8; j++) {
                    #pragma unroll
                    for (int c = 0; c < 2; c++) {
                        const int d = 8*j + 2*t4 + c;
                        g_vtf[vb0 + (size_t)d * NN + n0r] = __float2half_rn(v0[2*j + c]);
                        g_vtf[vb1 + (size_t)d * NN + n1r] = __float2half_rn(v1[2*j + c]);
                    }
                }
            }
        } else {
            float* p0 = out + (size_t)gr0 * CC + colw;
            float* p1 = out + (size_t)gr1 * CC + colw;
            #pragma unroll
            for (int j = 0; j < 8; j++) {
                *(float2*)(p0 + 8*j + 2*t4) = make_float2(v0[2*j], v0[2*j+1]);
                *(float2*)(p1 + 8*j + 2*t4) = make_float2(v1[2*j], v1[2*j+1]);
            }
        }
    }
}

// ---------------------------------------------------------------------------
// fp16 HMMA flash attention (128 threads, 64-q tile), SINGLE-TERM fp16 S/PV,
// fixed-max softmax, 3-stage cp.async ring, single barrier per key-tile.
// SMEM 56KB: Q fp16 [64][64] @0 (8K); stage s @8K+s*16K:
//   K fp16 [64][64] @+0 (8K), Vt fp16 [64 d][64 k] @+8K.
// ---------------------------------------------------------------------------
__device__ __forceinline__ uint32_t swz_qk(int row, int kbyte) {   // 128B rows
    return (uint32_t)(row * 128 + ((((kbyte >> 4) ^ row) & 7) << 4) + (kbyte & 15));
}

#define ATTN_SMEM (8192 + 3*16384)   // 57344
#define MAXB 13.0f

__global__ __launch_bounds__(128, 3)
void attn_kernel()
{
    extern __shared__ __align__(128) char smem[];
    const uint32_t sbu = smem_to_u32(smem);

    const int tid  = threadIdx.x;
    const int lane = tid & 31;
    const int w    = tid >> 5;     // 0..3
    const int wm   = w * 16;
    const int g = lane >> 2, t = lane & 3;

    const int bh = blockIdx.y;
    const int b  = bh >> 4, h = bh & 15;
    const int qt = blockIdx.x;     // 0..31

    const size_t qoff  = ((size_t)bh * NN + qt * 64) * HD;
    const size_t kbase = (size_t)bh * NN * HD;
    const size_t vtbase = (size_t)bh * HD * NN;

    const int amat = lane >> 3;
    const int arow_off = (amat & 1) * 8 + (lane & 7);
    const int akb_off  = (amat >> 1) * 16;
    const int brow_off = (amat >> 1) * 8 + (lane & 7);
    const int bkb_off  = (amat & 1) * 16;

    // ---- stage loader: K + Vt fp16, 64-key tile, 4 chunks/thread/buffer ----
    auto load_stage = [&](int kt, int slot) {
        const uint32_t base = sbu + 8192u + (uint32_t)slot * 16384u;
        #pragma unroll
        for (int c = 0; c < 4; c++) {
            const int idx = tid + 128 * c;
            const int row = idx >> 3;
            const int kc  = idx & 7;
            const uint32_t off = swz_qk(row, kc * 16);
            const size_t ks = kbase + (size_t)(kt * 64 + row) * HD + kc * 8;
            const size_t vs = vtbase + (size_t)row * NN + kt * 64 + kc * 8;
            cpa16(base + off,         g_kf + ks);
            cpa16(base + 8192 + off,  g_vtf + vs);
        }
    };

    load_stage(0, 0); CP_COMMIT();
    load_stage(1, 1); CP_COMMIT();

    // ---- load Q tile fp16 (plain 16B copies) ----
    #pragma unroll
    for (int c = 0; c < 4; c++) {
        const int idx = tid + 128 * c;
        const int row = idx >> 3;
        const int kc  = idx & 7;
        const uint32_t off = swz_qk(row, kc * 16);
        *(uint4*)(smem + off) = *(const uint4*)(g_qf + qoff + (size_t)row * HD + kc * 8);
    }
    __syncthreads();

    // ---- Q fragments (16 rows x 64 hd) ----
    uint32_t qf[4][4];
    #pragma unroll
    for (int kk = 0; kk < 4; kk++)
        ldsm4(sbu + swz_qk(wm + arow_off, kk*32 + akb_off), qf[kk]);

    float l0 = 0.f, l1 = 0.f;
    float O[8][4];
    #pragma unroll
    for (int j = 0; j < 8; j++)
        #pragma unroll
        for (int c = 0; c < 4; c++) O[j][c] = 0.f;

    for (int kt = 0; kt < NN / 64; kt++) {
        CP_WAIT1();                       // stage kt landed
        __syncthreads();                  // all warps past iter kt-1
        const uint32_t stb = sbu + 8192u + (uint32_t)(kt % 3) * 16384u;

        // ---- S = Q K^T (64 keys), single-term fp16 ----
        float S[8][4];
        #pragma unroll
        for (int j = 0; j < 8; j++)
            #pragma unroll
            for (int c = 0; c < 4; c++) S[j][c] = 0.f;

        #pragma unroll
        for (int kk = 0; kk < 4; kk++) {
            #pragma unroll
            for (int j2 = 0; j2 < 4; j2++) {
                const uint32_t off = swz_qk(j2*16 + brow_off, kk*32 + bkb_off);
                uint32_t bb[4];
                ldsm4(stb + off, bb);
                mma16816h(S[2*j2],   qf[kk], bb);
                mma16816h(S[2*j2+1], qf[kk], bb + 2);
            }
        }

        // ---- fixed-max softmax: p = ex2(s - MAXB); accumulate local sums ----
        #pragma unroll
        for (int j = 0; j < 8; j++) {
            S[j][0] = ex2(S[j][0] - MAXB);
            S[j][1] = ex2(S[j][1] - MAXB);
            S[j][2] = ex2(S[j][2] - MAXB);
            S[j][3] = ex2(S[j][3] - MAXB);
            l0 += S[j][0] + S[j][1];
            l1 += S[j][2] + S[j][3];
        }

        // ---- O += P V, single-term fp16 ----
        #pragma unroll
        for (int kk = 0; kk < 4; kk++) {
            uint32_t ph[4];
            ph[0] = packh2(S[2*kk][0],   S[2*kk][1]);
            ph[1] = packh2(S[2*kk][2],   S[2*kk][3]);
            ph[2] = packh2(S[2*kk+1][0], S[2*kk+1][1]);
            ph[3] = packh2(S[2*kk+1][2], S[2*kk+1][3]);
            #pragma unroll
            for (int jh = 0; jh < 4; jh++) {
                const uint32_t off = swz_qk(jh*16 + brow_off, kk*32 + bkb_off);
                uint32_t vv[4];
                ldsm4(stb + 8192 + off, vv);
                mma16816h(O[2*jh],   ph, vv);
                mma16816h(O[2*jh+1], ph, vv + 2);
            }
        }
        // prefetch kt+2 into slot (kt+2)%3 == (kt-1)%3 — no barrier needed
        if (kt + 2 < NN / 64) load_stage(kt + 2, (kt + 2) % 3);
        CP_COMMIT();                      // always commit (uniform accounting)
    }

    // ---- deferred row-sum reduction (once) ----
    l0 += __shfl_xor_sync(0xffffffffu, l0, 1);
    l0 += __shfl_xor_sync(0xffffffffu, l0, 2);
    l1 += __shfl_xor_sync(0xffffffffu, l1, 1);
    l1 += __shfl_xor_sync(0xffffffffu, l1, 2);

    // ---- epilogue: normalize, write bf16 hi/lo to g_oh/g_ol [B,N,C] ----
    const float inv0 = 1.0f / l0;
    const float inv1 = 1.0f / l1;
    const int q0 = qt * 64 + wm + g;
    const size_t p0 = ((size_t)b * NN + q0) * CC + h * HD;
    const size_t p1 = ((size_t)b * NN + q0 + 8) * CC + h * HD;
    #pragma unroll
    for (int j = 0; j < 8; j++) {
        uint32_t hi, lo;
        split_pair(O[j][0] * inv0, O[j][1] * inv0, hi, lo);
        *(uint32_t*)(g_oh + p0 + 8*j + 2*t) = hi;
        *(uint32_t*)(g_ol + p0 + 8*j + 2*t) = lo;
        split_pair(O[j][2] * inv1, O[j][3] * inv1, hi, lo);
        *(uint32_t*)(g_oh + p1 + 8*j + 2*t) = hi;
        *(uint32_t*)(g_ol + p1 + 8*j + 2*t) = lo;
    }
}

// ---------------------------------------------------------------------------
extern "C" void kernel_launch(void* const* d_in, const int* in_sizes, int n_in,
                              void* d_out, int out_size)
{
    const float* x        = (const float*)d_in[0];
    const float* qkv_w    = (const float*)d_in[1];
    const float* qkv_b    = (const float*)d_in[2];
    const float* q_norm_w = (const float*)d_in[3];
    const float* k_norm_w = (const float*)d_in[4];
    const float* proj_w   = (const float*)d_in[5];
    const float* proj_b   = (const float*)d_in[6];
    float* out = (float*)d_out;

    __nv_bfloat16 *xh, *xl, *wth, *wtl, *pwth, *pwtl, *oh, *ol;
    cudaGetSymbolAddress((void**)&xh,   g_xh);
    cudaGetSymbolAddress((void**)&xl,   g_xl);
    cudaGetSymbolAddress((void**)&wth,  g_wth);
    cudaGetSymbolAddress((void**)&wtl,  g_wtl);
    cudaGetSymbolAddress((void**)&pwth, g_pwth);
    cudaGetSymbolAddress((void**)&pwtl, g_pwtl);
    cudaGetSymbolAddress((void**)&oh,   g_oh);
    cudaGetSymbolAddress((void**)&ol,   g_ol);

    cudaFuncSetAttribute(hmma_gemm_ca,
                         cudaFuncAttributeMaxDynamicSharedMemorySize, GEMM_SMEM);
    cudaFuncSetAttribute(attn_kernel,
                         cudaFuncAttributeMaxDynamicSharedMemorySize, ATTN_SMEM);

    // Operand conversion
    convert_x_kernel<<<MROWS * CC / 1024, 256>>>(x);
    {
        dim3 tb(32, 8);
        transpose_convert_kernel<<<dim3(QKVN/32, CC/32), tb>>>(qkv_w, wth, wtl, CC, QKVN);
        transpose_convert_kernel<<<dim3(CC/32, CC/32), tb>>>(proj_w, pwth, pwtl, CC, CC);
    }
    // QKV GEMM + bias + fused rmsnorm -> fp16 q/k, fp16 v^T
    {
        dim3 grid(QKVN / 128, MROWS / 128);   // 24 x 32
        hmma_gemm_ca<<<grid, 256, GEMM_SMEM>>>(xh, xl, wth, wtl, qkv_b, nullptr,
                                               q_norm_w, k_norm_w, 0);
    }
    // Flash attention (fp16 single-term, 128 threads, 64-q tile)
    {
        dim3 grid(NN / 64, BB * HH);          // 32 x 32
        attn_kernel<<<grid, 128, ATTN_SMEM>>>();
    }
    // Output projection (bf16 3-term)
    {
        dim3 grid(CC / 128, MROWS / 128);     // 8 x 32
        hmma_gemm_ca<<<grid, 256, GEMM_SMEM>>>(oh, ol, pwth, pwtl, proj_b, out,
                                               nullptr, nullptr, 1);
    }
}

// round 17
// speedup vs baseline: 1.8245x; 1.2506x over previous
#include <cuda_runtime.h>
#include <cuda_fp16.h>
#include <stdint.h>
#include <math.h>

#define BB 2
#define NN 2048
#define CC 1024
#define HH 16
#define HD 64
#define MROWS (BB*NN)      // 4096
#define QKVN  (3*CC)       // 3072
#define QKV_ELEMS (BB*HH*NN*HD)   // 4194304

// Scratch (static device arrays — allowed)
__device__ __half g_qf[QKV_ELEMS];                 // q fp16 [B,H,N,hd]
__device__ __half g_kf[QKV_ELEMS];                 // k fp16 [B,H,N,hd]
__device__ __half g_vtf[QKV_ELEMS];                // v^T fp16 [B,H,hd,N]
__device__ __half g_xh[MROWS*CC], g_xl[MROWS*CC];  // x fp16 hi/residual
__device__ __half g_wtf[QKVN*CC];                  // qkv_w^T fp16
__device__ __half g_pwtf[CC*CC];                   // proj_w^T fp16
__device__ __half g_oh[MROWS*CC], g_ol[MROWS*CC];  // attn out fp16 hi/residual

// ---------------------------------------------------------------------------
// helpers
// ---------------------------------------------------------------------------
__device__ __forceinline__ uint32_t smem_to_u32(const void* p) {
    uint32_t a;
    asm("{ .reg .u64 t; cvta.to.shared.u64 t, %1; cvt.u32.u64 %0, t; }"
        : "=r"(a) : "l"(p));
    return a;
}

__device__ __forceinline__ void ldsm4(uint32_t addr, uint32_t* r) {
    asm volatile("ldmatrix.sync.aligned.m8n8.x4.shared.b16 {%0,%1,%2,%3}, [%4];"
                 : "=r"(r[0]), "=r"(r[1]), "=r"(r[2]), "=r"(r[3]) : "r"(addr));
}

__device__ __forceinline__ void mma16816h(float* d, const uint32_t* a,
                                          const uint32_t* b) {
    asm volatile(
        "mma.sync.aligned.m16n8k16.row.col.f32.f16.f16.f32 "
        "{%0,%1,%2,%3}, {%4,%5,%6,%7}, {%8,%9}, {%0,%1,%2,%3};"
        : "+f"(d[0]), "+f"(d[1]), "+f"(d[2]), "+f"(d[3])
        : "r"(a[0]), "r"(a[1]), "r"(a[2]), "r"(a[3]), "r"(b[0]), "r"(b[1]));
}

__device__ __forceinline__ float ex2(float x) {
    float r; asm("ex2.approx.f32 %0, %1;" : "=f"(r) : "f"(x)); return r;
}

__device__ __forceinline__ void cpa16(uint32_t dst, const void* src) {
    asm volatile("cp.async.cg.shared.global [%0], [%1], 16;" :: "r"(dst), "l"(src));
}
#define CP_COMMIT() asm volatile("cp.async.commit_group;" ::: "memory")
#define CP_WAIT1()  asm volatile("cp.async.wait_group 1;" ::: "memory")

// pack (lo, hi) floats into one f16x2 register
__device__ __forceinline__ uint32_t packh2(float lo, float hi) {
    uint32_t r;
    asm("cvt.rn.f16x2.f32 %0, %1, %2;" : "=r"(r) : "f"(hi), "f"(lo));
    return r;
}

// fp16 hi + fp16 residual pair
__device__ __forceinline__ void split_pairh(float p0, float p1,
                                            uint32_t& hi, uint32_t& lo) {
    __half h0 = __float2half_rn(p0);
    __half h1 = __float2half_rn(p1);
    hi = ((uint32_t)__half_as_ushort(h1) << 16) | __half_as_ushort(h0);
    lo = packh2(p0 - __half2float(h0), p1 - __half2float(h1));
}

// ---------------------------------------------------------------------------
// x -> fp16 hi/residual (same layout)
// ---------------------------------------------------------------------------
__global__ __launch_bounds__(256)
void convert_x_kernel(const float* __restrict__ x)
{
    const int i = (blockIdx.x * 256 + threadIdx.x) * 4;
    float4 f = *(const float4*)(x + i);
    uint32_t h01, l01, h23, l23;
    split_pairh(f.x, f.y, h01, l01);
    split_pairh(f.z, f.w, h23, l23);
    *(uint2*)(g_xh + i) = make_uint2(h01, h23);
    *(uint2*)(g_xl + i) = make_uint2(l01, l23);
}

// ---------------------------------------------------------------------------
// Weight transpose+convert: src fp32 [R][C] -> dst fp16 [C][R]
// ---------------------------------------------------------------------------
__global__ __launch_bounds__(256)
void transpose_convert_kernel(const float* __restrict__ src,
                              __half* __restrict__ dst, int R, int C)
{
    __shared__ float t[32][33];
    const int bx = blockIdx.x * 32;   // over C
    const int by = blockIdx.y * 32;   // over R
    const int x = threadIdx.x, y0 = threadIdx.y;
    #pragma unroll
    for (int i = y0; i < 32; i += 8)
        t[i][x] = src[(size_t)(by + i) * C + bx + x];
    __syncthreads();
    #pragma unroll
    for (int i = y0; i < 32; i += 8)
        dst[(size_t)(bx + i) * R + by + x] = __float2half_rn(t[x][i]);
}

// ---------------------------------------------------------------------------
// cp.async 3-stage fp16 HMMA GEMM, 2-term (A hi+res, B single):
// D = (Ah+Al) * B^T. Single barrier per k-iteration (round-15 scheme).
// Stage (24KB): Ah @0, Al @8K, B @16K, each [128][32] fp16 swizzled.
// mode 0: QKV epilogue -> bias + fused rmsnorm q/k -> fp16 scatter;
//         v third written TRANSPOSED fp16 into g_vtf ([B,H,hd,N]).
// mode 1: proj epilogue -> bias -> fp32 row-major out
// ---------------------------------------------------------------------------
__device__ __forceinline__ uint32_t swz(int row, int kbyte) {   // 64B rows
    return (uint32_t)(row * 64 + ((kbyte & 48) ^ (((row >> 1) & 3) << 4)) + (kbyte & 15));
}

#define GEMM_SMEM (3*24576)    // 73728

__global__ __launch_bounds__(256, 2)
void hmma_gemm_ca(const __half* __restrict__ Ah, const __half* __restrict__ Al,
                  const __half* __restrict__ Bf,
                  const float* __restrict__ bias, float* __restrict__ out,
                  const float* __restrict__ qnw, const float* __restrict__ knw,
                  int mode)
{
    extern __shared__ __align__(128) char sb[];
    const uint32_t sbu = smem_to_u32(sb);

    const int tid  = threadIdx.x;
    const int lane = tid & 31;
    const int w    = tid >> 5;
    const int wm   = (w >> 1) * 32;
    const int wn   = (w & 1) * 64;
    const int row0 = blockIdx.y * 128;
    const int col0 = blockIdx.x * 128;

    const int amat = lane >> 3;
    const int arow_off = (amat & 1) * 8 + (lane & 7);
    const int akb_off  = (amat >> 1) * 16;
    const int brow_off = (amat >> 1) * 8 + (lane & 7);
    const int bkb_off  = (amat & 1) * 16;

    const int ch_row0 = (tid + 0)   >> 2, ch_kc0 = (tid + 0)   & 3;
    const int ch_row1 = (tid + 256) >> 2, ch_kc1 = (tid + 256) & 3;

    auto load_stage = [&](int kt, int slot) {
        const uint32_t base = sbu + (uint32_t)slot * 24576u;
        {
            const uint32_t off = swz(ch_row0, ch_kc0 * 16);
            const size_t as = (size_t)(row0 + ch_row0) * CC + kt * 32 + ch_kc0 * 8;
            const size_t bs = (size_t)(col0 + ch_row0) * CC + kt * 32 + ch_kc0 * 8;
            cpa16(base + off,         Ah + as);
            cpa16(base + 8192 + off,  Al + as);
            cpa16(base + 16384 + off, Bf + bs);
        }
        {
            const uint32_t off = swz(ch_row1, ch_kc1 * 16);
            const size_t as = (size_t)(row0 + ch_row1) * CC + kt * 32 + ch_kc1 * 8;
            const size_t bs = (size_t)(col0 + ch_row1) * CC + kt * 32 + ch_kc1 * 8;
            cpa16(base + off,         Ah + as);
            cpa16(base + 8192 + off,  Al + as);
            cpa16(base + 16384 + off, Bf + bs);
        }
    };

    float D[2][8][4];
    #pragma unroll
    for (int i = 0; i < 2; i++)
        #pragma unroll
        for (int j = 0; j < 8; j++)
            #pragma unroll
            for (int c = 0; c < 4; c++) D[i][j][c] = 0.f;

    load_stage(0, 0); CP_COMMIT();
    load_stage(1, 1); CP_COMMIT();

    for (int t = 0; t < 32; t++) {
        CP_WAIT1();                       // stage t landed
        __syncthreads();                  // all warps past iter t-1
        const uint32_t stb = sbu + (uint32_t)(t % 3) * 24576u;

        #pragma unroll
        for (int k16 = 0; k16 < 2; k16++) {
            const int kb = k16 * 32;
            uint32_t a_hi[2][4], a_lo[2][4];
            #pragma unroll
            for (int i = 0; i < 2; i++) {
                const uint32_t aoff = swz(wm + 16*i + arow_off, kb + akb_off);
                ldsm4(stb + aoff, a_hi[i]);
                ldsm4(stb + 8192 + aoff, a_lo[i]);
            }
            #pragma unroll
            for (int j2 = 0; j2 < 4; j2++) {
                const uint32_t boff = swz(wn + j2*16 + brow_off, kb + bkb_off);
                uint32_t b[4];
                ldsm4(stb + 16384 + boff, b);
                #pragma unroll
                for (int i = 0; i < 2; i++) {
                    mma16816h(D[i][2*j2],   a_hi[i], b);
                    mma16816h(D[i][2*j2],   a_lo[i], b);
                    mma16816h(D[i][2*j2+1], a_hi[i], b + 2);
                    mma16816h(D[i][2*j2+1], a_lo[i], b + 2);
                }
            }
        }
        // prefetch iter t+2 into slot (t+2)%3 == (t-1)%3 — no barrier needed
        if (t + 2 < 32) load_stage(t + 2, (t + 2) % 3);
        CP_COMMIT();                      // always commit (uniform accounting)
    }

    // ---- Epilogue ----
    const int g = lane >> 2;
    const int t4 = lane & 3;
    const int colw = col0 + wn;
    const int s   = (mode == 0) ? (colw >> 10) : 3;
    const int h   = (colw & 1023) >> 6;
    const float* nw = (s == 0) ? qnw : knw;
    const float postscale = (s == 0) ? 0.18033688011112042f : 1.0f; // 0.125*log2(e)

    #pragma unroll
    for (int i = 0; i < 2; i++) {
        float v0[16], v1[16];
        #pragma unroll
        for (int j = 0; j < 8; j++) {
            const float bj0 = bias[colw + 8*j + 2*t4];
            const float bj1 = bias[colw + 8*j + 2*t4 + 1];
            v0[2*j]   = D[i][j][0] + bj0;
            v0[2*j+1] = D[i][j][1] + bj1;
            v1[2*j]   = D[i][j][2] + bj0;
            v1[2*j+1] = D[i][j][3] + bj1;
        }
        const int gr0 = row0 + wm + 16*i + g;
        const int gr1 = gr0 + 8;
        if (mode == 0) {
            const int b0r = gr0 >> 11, n0r = gr0 & 2047;
            const int b1r = gr1 >> 11, n1r = gr1 & 2047;
            if (s < 2) {
                float ss0 = 0.f, ss1 = 0.f;
                #pragma unroll
                for (int c = 0; c < 16; c++) { ss0 += v0[c]*v0[c]; ss1 += v1[c]*v1[c]; }
                ss0 += __shfl_xor_sync(0xffffffffu, ss0, 1);
                ss0 += __shfl_xor_sync(0xffffffffu, ss0, 2);
                ss1 += __shfl_xor_sync(0xffffffffu, ss1, 1);
                ss1 += __shfl_xor_sync(0xffffffffu, ss1, 2);
                const float n0 = rsqrtf(ss0 * (1.0f/64.0f) + 1e-6f) * postscale;
                const float n1 = rsqrtf(ss1 * (1.0f/64.0f) + 1e-6f) * postscale;
                #pragma unroll
                for (int j = 0; j < 8; j++) {
                    const float w0 = nw[8*j + 2*t4], w1 = nw[8*j + 2*t4 + 1];
                    v0[2*j]   *= n0 * w0;  v0[2*j+1] *= n0 * w1;
                    v1[2*j]   *= n1 * w0;  v1[2*j+1] *= n1 * w1;
                }
                __half* dst = (s == 0) ? g_qf : g_kf;
                const size_t p0 = (((size_t)(b0r * HH + h) * NN) + n0r) * HD;
                const size_t p1 = (((size_t)(b1r * HH + h) * NN) + n1r) * HD;
                #pragma unroll
                for (int j = 0; j < 8; j++) {
                    *(uint32_t*)(dst + p0 + 8*j + 2*t4) = packh2(v0[2*j], v0[2*j+1]);
                    *(uint32_t*)(dst + p1 + 8*j + 2*t4) = packh2(v1[2*j], v1[2*j+1]);
                }
            } else {
                // v third: write TRANSPOSED fp16 into g_vtf [B,H,hd,N]
                const size_t vb0 = (size_t)(b0r * HH + h) * HD * NN;
                const size_t vb1 = (size_t)(b1r * HH + h) * HD * NN;
                #pragma unroll
                for (int j = 0; j < 8; j++) {
                    #pragma unroll
                    for (int c = 0; c < 2; c++) {
                        const int d = 8*j + 2*t4 + c;
                        g_vtf[vb0 + (size_t)d * NN + n0r] = __float2half_rn(v0[2*j + c]);
                        g_vtf[vb1 + (size_t)d * NN + n1r] = __float2half_rn(v1[2*j + c]);
                    }
                }
            }
        } else {
            float* p0 = out + (size_t)gr0 * CC + colw;
            float* p1 = out + (size_t)gr1 * CC + colw;
            #pragma unroll
            for (int j = 0; j < 8; j++) {
                *(float2*)(p0 + 8*j + 2*t4) = make_float2(v0[2*j], v0[2*j+1]);
                *(float2*)(p1 + 8*j + 2*t4) = make_float2(v1[2*j], v1[2*j+1]);
            }
        }
    }
}

// ---------------------------------------------------------------------------
// fp16 HMMA flash attention (128 threads, 64-q tile, 3 blocks/SM),
// single-term fp16 S/PV, fixed-max softmax, 3-stage ring, 1 barrier/tile.
// SMEM 56KB: Q fp16 [64][64] @0 (8K); stage s @8K+s*16K:
//   K fp16 [64][64] @+0 (8K), Vt fp16 [64 d][64 k] @+8K.
// ---------------------------------------------------------------------------
__device__ __forceinline__ uint32_t swz_qk(int row, int kbyte) {   // 128B rows
    return (uint32_t)(row * 128 + ((((kbyte >> 4) ^ row) & 7) << 4) + (kbyte & 15));
}

#define ATTN_SMEM (8192 + 3*16384)   // 57344
#define MAXB 13.0f

__global__ __launch_bounds__(128, 3)
void attn_kernel()
{
    extern __shared__ __align__(128) char smem[];
    const uint32_t sbu = smem_to_u32(smem);

    const int tid  = threadIdx.x;
    const int lane = tid & 31;
    const int w    = tid >> 5;     // 0..3
    const int wm   = w * 16;
    const int g = lane >> 2, t = lane & 3;

    const int bh = blockIdx.y;
    const int b  = bh >> 4, h = bh & 15;
    const int qt = blockIdx.x;     // 0..31

    const size_t qoff  = ((size_t)bh * NN + qt * 64) * HD;
    const size_t kbase = (size_t)bh * NN * HD;
    const size_t vtbase = (size_t)bh * HD * NN;

    const int amat = lane >> 3;
    const int arow_off = (amat & 1) * 8 + (lane & 7);
    const int akb_off  = (amat >> 1) * 16;
    const int brow_off = (amat >> 1) * 8 + (lane & 7);
    const int bkb_off  = (amat & 1) * 16;

    auto load_stage = [&](int kt, int slot) {
        const uint32_t base = sbu + 8192u + (uint32_t)slot * 16384u;
        #pragma unroll
        for (int c = 0; c < 4; c++) {
            const int idx = tid + 128 * c;
            const int row = idx >> 3;
            const int kc  = idx & 7;
            const uint32_t off = swz_qk(row, kc * 16);
            const size_t ks = kbase + (size_t)(kt * 64 + row) * HD + kc * 8;
            const size_t vs = vtbase + (size_t)row * NN + kt * 64 + kc * 8;
            cpa16(base + off,         g_kf + ks);
            cpa16(base + 8192 + off,  g_vtf + vs);
        }
    };

    load_stage(0, 0); CP_COMMIT();
    load_stage(1, 1); CP_COMMIT();

    // ---- load Q tile fp16 (plain 16B copies) ----
    #pragma unroll
    for (int c = 0; c < 4; c++) {
        const int idx = tid + 128 * c;
        const int row = idx >> 3;
        const int kc  = idx & 7;
        const uint32_t off = swz_qk(row, kc * 16);
        *(uint4*)(smem + off) = *(const uint4*)(g_qf + qoff + (size_t)row * HD + kc * 8);
    }
    __syncthreads();

    // ---- Q fragments (16 rows x 64 hd) ----
    uint32_t qf[4][4];
    #pragma unroll
    for (int kk = 0; kk < 4; kk++)
        ldsm4(sbu + swz_qk(wm + arow_off, kk*32 + akb_off), qf[kk]);

    float l0 = 0.f, l1 = 0.f;
    float O[8][4];
    #pragma unroll
    for (int j = 0; j < 8; j++)
        #pragma unroll
        for (int c = 0; c < 4; c++) O[j][c] = 0.f;

    for (int kt = 0; kt < NN / 64; kt++) {
        CP_WAIT1();                       // stage kt landed
        __syncthreads();                  // all warps past iter kt-1
        const uint32_t stb = sbu + 8192u + (uint32_t)(kt % 3) * 16384u;

        // ---- S = Q K^T (64 keys), single-term fp16 ----
        float S[8][4];
        #pragma unroll
        for (int j = 0; j < 8; j++)
            #pragma unroll
            for (int c = 0; c < 4; c++) S[j][c] = 0.f;

        #pragma unroll
        for (int kk = 0; kk < 4; kk++) {
            #pragma unroll
            for (int j2 = 0; j2 < 4; j2++) {
                const uint32_t off = swz_qk(j2*16 + brow_off, kk*32 + bkb_off);
                uint32_t bb[4];
                ldsm4(stb + off, bb);
                mma16816h(S[2*j2],   qf[kk], bb);
                mma16816h(S[2*j2+1], qf[kk], bb + 2);
            }
        }

        // ---- fixed-max softmax ----
        #pragma unroll
        for (int j = 0; j < 8; j++) {
            S[j][0] = ex2(S[j][0] - MAXB);
            S[j][1] = ex2(S[j][1] - MAXB);
            S[j][2] = ex2(S[j][2] - MAXB);
            S[j][3] = ex2(S[j][3] - MAXB);
            l0 += S[j][0] + S[j][1];
            l1 += S[j][2] + S[j][3];
        }

        // ---- O += P V, single-term fp16 ----
        #pragma unroll
        for (int kk = 0; kk < 4; kk++) {
            uint32_t ph[4];
            ph[0] = packh2(S[2*kk][0],   S[2*kk][1]);
            ph[1] = packh2(S[2*kk][2],   S[2*kk][3]);
            ph[2] = packh2(S[2*kk+1][0], S[2*kk+1][1]);
            ph[3] = packh2(S[2*kk+1][2], S[2*kk+1][3]);
            #pragma unroll
            for (int jh = 0; jh < 4; jh++) {
                const uint32_t off = swz_qk(jh*16 + brow_off, kk*32 + bkb_off);
                uint32_t vv[4];
                ldsm4(stb + 8192 + off, vv);
                mma16816h(O[2*jh],   ph, vv);
                mma16816h(O[2*jh+1], ph, vv + 2);
            }
        }
        if (kt + 2 < NN / 64) load_stage(kt + 2, (kt + 2) % 3);
        CP_COMMIT();                      // always commit (uniform accounting)
    }

    // ---- deferred row-sum reduction (once) ----
    l0 += __shfl_xor_sync(0xffffffffu, l0, 1);
    l0 += __shfl_xor_sync(0xffffffffu, l0, 2);
    l1 += __shfl_xor_sync(0xffffffffu, l1, 1);
    l1 += __shfl_xor_sync(0xffffffffu, l1, 2);

    // ---- epilogue: normalize, write fp16 hi/res to g_oh/g_ol [B,N,C] ----
    const float inv0 = 1.0f / l0;
    const float inv1 = 1.0f / l1;
    const int q0 = qt * 64 + wm + g;
    const size_t p0 = ((size_t)b * NN + q0) * CC + h * HD;
    const size_t p1 = ((size_t)b * NN + q0 + 8) * CC + h * HD;
    #pragma unroll
    for (int j = 0; j < 8; j++) {
        uint32_t hi, lo;
        split_pairh(O[j][0] * inv0, O[j][1] * inv0, hi, lo);
        *(uint32_t*)(g_oh + p0 + 8*j + 2*t) = hi;
        *(uint32_t*)(g_ol + p0 + 8*j + 2*t) = lo;
        split_pairh(O[j][2] * inv1, O[j][3] * inv1, hi, lo);
        *(uint32_t*)(g_oh + p1 + 8*j + 2*t) = hi;
        *(uint32_t*)(g_ol + p1 + 8*j + 2*t) = lo;
    }
}

// ---------------------------------------------------------------------------
extern "C" void kernel_launch(void* const* d_in, const int* in_sizes, int n_in,
                              void* d_out, int out_size)
{
    const float* x        = (const float*)d_in[0];
    const float* qkv_w    = (const float*)d_in[1];
    const float* qkv_b    = (const float*)d_in[2];
    const float* q_norm_w = (const float*)d_in[3];
    const float* k_norm_w = (const float*)d_in[4];
    const float* proj_w   = (const float*)d_in[5];
    const float* proj_b   = (const float*)d_in[6];
    float* out = (float*)d_out;

    __half *xh, *xl, *wtf, *pwtf, *oh, *ol;
    cudaGetSymbolAddress((void**)&xh,   g_xh);
    cudaGetSymbolAddress((void**)&xl,   g_xl);
    cudaGetSymbolAddress((void**)&wtf,  g_wtf);
    cudaGetSymbolAddress((void**)&pwtf, g_pwtf);
    cudaGetSymbolAddress((void**)&oh,   g_oh);
    cudaGetSymbolAddress((void**)&ol,   g_ol);

    cudaFuncSetAttribute(hmma_gemm_ca,
                         cudaFuncAttributeMaxDynamicSharedMemorySize, GEMM_SMEM);
    cudaFuncSetAttribute(attn_kernel,
                         cudaFuncAttributeMaxDynamicSharedMemorySize, ATTN_SMEM);

    // Operand conversion
    convert_x_kernel<<<MROWS * CC / 1024, 256>>>(x);
    {
        dim3 tb(32, 8);
        transpose_convert_kernel<<<dim3(QKVN/32, CC/32), tb>>>(qkv_w, wtf, CC, QKVN);
        transpose_convert_kernel<<<dim3(CC/32, CC/32), tb>>>(proj_w, pwtf, CC, CC);
    }
    // QKV GEMM + bias + fused rmsnorm -> fp16 q/k, fp16 v^T
    {
        dim3 grid(QKVN / 128, MROWS / 128);   // 24 x 32
        hmma_gemm_ca<<<grid, 256, GEMM_SMEM>>>(xh, xl, wtf, qkv_b, nullptr,
                                               q_norm_w, k_norm_w, 0);
    }
    // Flash attention (fp16 single-term, 128 threads, 64-q tile)
    {
        dim3 grid(NN / 64, BB * HH);          // 32 x 32
        attn_kernel<<<grid, 128, ATTN_SMEM>>>();
    }
    // Output projection (fp16 2-term)
    {
        dim3 grid(CC / 128, MROWS / 128);     // 8 x 32
        hmma_gemm_ca<<<grid, 256, GEMM_SMEM>>>(oh, ol, pwtf, proj_b, out,
                                               nullptr, nullptr, 1);
    }
}